// round 4
// baseline (speedup 1.0000x reference)
#include <cuda_runtime.h>
#include <math.h>
#include <stdint.h>

#define D      200
#define NE     40000
#define TOT    160000
#define EHALF  80000
#define R2     200
#define NB     1024
#define EPSV   1e-5f

// ---------------- scratch (static device globals; no allocation) ----------------
__device__ float g_deg[2 * NE];
__device__ float g_norm[TOT];
__device__ int   g_cnt_in[NE], g_cnt_out[NE];
__device__ int   g_off_in[NE + 1], g_off_out[NE + 1];
__device__ int   g_cur_in[NE], g_cur_out[NE];
__device__ int   g_ce_in[EHALF], g_ce_out[EHALF];
__device__ float g_relbuf[(R2 + 1) * D];
__device__ float g_r1[R2 * D];
__device__ float g_r2[R2 * D];
__device__ float g_Bcat[3 * D * D];
__device__ float g_Q[(size_t)TOT * D];
__device__ float g_P[(size_t)TOT * D];
__device__ float g_Min[NE * D];
__device__ float g_Mout[NE * D];
__device__ float g_agg[NE * D];
__device__ float g_x1[NE * D];
__device__ float g_sum[D], g_sumsq[D], g_cA[D], g_cB[D];

// packed f32x2 FMA (sm_103a FFMA2 — PTX only)
__device__ __forceinline__ void fma2(float2& c, float2 a, float2 b) {
    unsigned long long cc = *reinterpret_cast<const unsigned long long*>(&c);
    unsigned long long aa = *reinterpret_cast<const unsigned long long*>(&a);
    unsigned long long bb = *reinterpret_cast<const unsigned long long*>(&b);
    asm("fma.rn.f32x2 %0, %1, %2, %0;" : "+l"(cc) : "l"(aa), "l"(bb));
    c = *reinterpret_cast<float2*>(&cc);
}

// ---------------- degree + per-side dst counts ----------------
__global__ void degcnt_k(const int* __restrict__ ei, float* __restrict__ deg,
                         int* __restrict__ cin, int* __restrict__ cout) {
    int i = blockIdx.x * blockDim.x + threadIdx.x;
    if (i < TOT) {
        int off = (i >= EHALF) ? NE : 0;
        atomicAdd(&deg[off + ei[i]], 1.0f);
        int dst = ei[TOT + i];
        if (i < EHALF) atomicAdd(&cin[dst], 1);
        else           atomicAdd(&cout[dst], 1);
    }
}

__global__ void norm_k(const int* __restrict__ ei, const float* __restrict__ deg,
                       float* __restrict__ nrm) {
    int i = blockIdx.x * blockDim.x + threadIdx.x;
    if (i < TOT) {
        int off = (i >= EHALF) ? NE : 0;
        float a = deg[off + ei[i]];
        float b = deg[off + ei[TOT + i]];
        float va = (a > 0.f) ? rsqrtf(a) : 0.f;
        float vb = (b > 0.f) ? rsqrtf(b) : 0.f;
        nrm[i] = va * vb;
    }
}

// ---------------- CSR scan + fill ----------------
#define SCAN_T 1024
__global__ void scan_k(const int* __restrict__ cnt, int* __restrict__ off,
                       int* __restrict__ cur, int total) {
    __shared__ int part[SCAN_T];
    int t = threadIdx.x;
    const int CH = (NE + SCAN_T - 1) / SCAN_T;
    int base = t * CH;
    int s = 0;
    for (int i = 0; i < CH; i++) {
        int idx = base + i;
        if (idx < NE) s += cnt[idx];
    }
    part[t] = s;
    __syncthreads();
    for (int d = 1; d < SCAN_T; d <<= 1) {
        int v = (t >= d) ? part[t - d] : 0;
        __syncthreads();
        part[t] += v;
        __syncthreads();
    }
    int run = (t > 0) ? part[t - 1] : 0;
    for (int i = 0; i < CH; i++) {
        int idx = base + i;
        if (idx < NE) {
            off[idx] = run;
            cur[idx] = run;
            run += cnt[idx];
        }
    }
    if (t == SCAN_T - 1) off[NE] = total;
}

__global__ void fill_k(const int* __restrict__ ei, int* __restrict__ cur_in,
                       int* __restrict__ cur_out, int* __restrict__ ce_in,
                       int* __restrict__ ce_out) {
    int e = blockIdx.x * blockDim.x + threadIdx.x;
    if (e < TOT) {
        int dst = ei[TOT + e];
        if (e < EHALF) { int p = atomicAdd(&cur_in[dst], 1);  ce_in[p] = e; }
        else           { int p = atomicAdd(&cur_out[dst], 1); ce_out[p] = e; }
    }
}

// ---------------- Bcat = [w_in ; w_out ; diag(loop_rel)@w_loop] ----------------
__global__ void prep_bcat_k(const float* __restrict__ w_in, const float* __restrict__ w_out,
                            const float* __restrict__ w_loop, const float* __restrict__ lr,
                            float* __restrict__ Bc) {
    int i = blockIdx.x * blockDim.x + threadIdx.x;
    if (i >= 3 * D * D) return;
    int r = i / D, c = i - r * D;
    float v;
    if (r < D)            v = w_in[r * D + c];
    else if (r < 2 * D)   v = w_out[(r - D) * D + c];
    else                  v = lr[r - 2 * D] * w_loop[(r - 2 * D) * D + c];
    Bc[i] = v;
}

// ---------------- qualifier feature build (float2) ----------------
__global__ void build_q_k(const float* __restrict__ x, const float* __restrict__ rel,
                          const int* __restrict__ qe, const int* __restrict__ qr,
                          float* __restrict__ Q) {
    int e = blockIdx.x;
    int f = threadIdx.x;
    if (f >= D / 2) return;
    int e0 = qe[e], e1 = qe[TOT + e];
    int r0 = qr[e], r1 = qr[TOT + e];
    float2 a = ((const float2*)(x + (size_t)e0 * D))[f];
    float2 b = ((const float2*)(rel + (size_t)r0 * D))[f];
    float2 c = ((const float2*)(x + (size_t)e1 * D))[f];
    float2 d = ((const float2*)(rel + (size_t)r1 * D))[f];
    float2 o;
    o.x = a.x * b.x + c.x * d.x;
    o.y = a.y * b.y + c.y * d.y;
    ((float2*)(Q + (size_t)e * D))[f] = o;
}

// ---------------- cp.async pipelined FFMA2 GEMM (segmented A, fused epilogues) ----------------
// MODE 0: C[gm] = acc (plain store)
// MODE 1: C[gm] = x[ei[gm]] * (0.5*rel[et[gm]] + 0.5*acc)
constexpr int BM = 128, BK = 10, NT = 256, NSTG = 3;
constexpr int BROW = 208;            // padded B tile row (floats), 16B-aligned groups of 52

template <int MODE, int NSEG>
__global__ __launch_bounds__(NT, 2)
void gemm_k(const float* A0, const float* A1, const float* A2,
            const float* __restrict__ Bw, float* C, int M,
            const int* __restrict__ ei, const int* __restrict__ et,
            const float* __restrict__ x, const float* __restrict__ rel) {
    __shared__ __align__(16) float As[NSTG][BM * BK];
    __shared__ __align__(16) float Bs[NSTG][BK * BROW];

    const int t  = threadIdx.x;
    const int tx = t & 3;            // column group 0..3 (52-float padded groups)
    const int ty = t >> 2;           // row pair 0..63
    const int m0 = blockIdx.x * BM;
    constexpr int NIT = NSEG * (D / BK);

    uint32_t sA = (uint32_t)__cvta_generic_to_shared(&As[0][0]);
    uint32_t sB = (uint32_t)__cvta_generic_to_shared(&Bs[0][0]);

    const float* segs[3] = {A0, A1, A2};

    auto issue_tile = [&](int tile) {
        int s = tile % NSTG;
        int seg = (NSEG == 1) ? 0 : tile / (D / BK);
        int k0 = tile * BK - seg * D;          // column within segment
        const float* Ause = segs[seg];
        for (int i = t; i < BM * BK / 2; i += NT) {       // 640 8B chunks
            int r = i / 5, cc = i - r * 5;
            int gm = m0 + r;
            const float* src = Ause + (size_t)gm * D + k0 + cc * 2;
            int sz = (gm < M) ? 8 : 0;
            asm volatile("cp.async.ca.shared.global [%0], [%1], 8, %2;\n"
                         :: "r"(sA + (uint32_t)((s * BM * BK + r * BK + cc * 2) * 4)),
                            "l"(src), "r"(sz));
        }
        int kb = tile * BK;                               // row in Bcat (global K index)
        for (int i = t; i < BK * (D / 2); i += NT) {      // 1000 8B chunks
            int rr = i / (D / 2), cc2 = i - rr * (D / 2); // cc2 in [0,100)
            int grp = cc2 / 25, off = cc2 - grp * 25;
            const float* src = Bw + (size_t)(kb + rr) * D + cc2 * 2;
            asm volatile("cp.async.ca.shared.global [%0], [%1], 8;\n"
                         :: "r"(sB + (uint32_t)((s * BK * BROW + rr * BROW + grp * 52 + off * 2) * 4)),
                            "l"(src));
        }
        asm volatile("cp.async.commit_group;\n");
    };

    issue_tile(0);
    issue_tile(1);

    float2 acc0[25], acc1[25];
#pragma unroll
    for (int j = 0; j < 25; j++) {
        acc0[j] = make_float2(0.f, 0.f);
        acc1[j] = make_float2(0.f, 0.f);
    }

    const int r0 = 2 * ty * BK, r1 = (2 * ty + 1) * BK;
    for (int it = 0; it < NIT; it++) {
        asm volatile("cp.async.wait_group 1;\n");
        __syncthreads();
        const float* as = &As[it % NSTG][0];
        const float* bs = &Bs[it % NSTG][0];
#pragma unroll
        for (int kk = 0; kk < BK; kk += 2) {
            float2 a0 = *(const float2*)(as + r0 + kk);
            float2 a1 = *(const float2*)(as + r1 + kk);
            float2 a00 = make_float2(a0.x, a0.x), a01 = make_float2(a0.y, a0.y);
            float2 a10 = make_float2(a1.x, a1.x), a11 = make_float2(a1.y, a1.y);
            const float* b0p = bs + kk * BROW + tx * 52;
            const float* b1p = b0p + BROW;
#pragma unroll
            for (int j4 = 0; j4 < 12; j4++) {
                float4 v0 = *(const float4*)(b0p + j4 * 4);
                float4 v1 = *(const float4*)(b1p + j4 * 4);
                float2 v0a = make_float2(v0.x, v0.y), v0b = make_float2(v0.z, v0.w);
                float2 v1a = make_float2(v1.x, v1.y), v1b = make_float2(v1.z, v1.w);
                fma2(acc0[2 * j4],     a00, v0a);
                fma2(acc0[2 * j4 + 1], a00, v0b);
                fma2(acc1[2 * j4],     a10, v0a);
                fma2(acc1[2 * j4 + 1], a10, v0b);
                fma2(acc0[2 * j4],     a01, v1a);
                fma2(acc0[2 * j4 + 1], a01, v1b);
                fma2(acc1[2 * j4],     a11, v1a);
                fma2(acc1[2 * j4 + 1], a11, v1b);
            }
            float2 v0l = *(const float2*)(b0p + 48);
            float2 v1l = *(const float2*)(b1p + 48);
            fma2(acc0[24], a00, v0l);
            fma2(acc1[24], a10, v0l);
            fma2(acc0[24], a01, v1l);
            fma2(acc1[24], a11, v1l);
        }
        __syncthreads();
        if (it + 2 < NIT) issue_tile(it + 2);
        else asm volatile("cp.async.commit_group;\n");
    }

#pragma unroll
    for (int rr = 0; rr < 2; rr++) {
        int gm = m0 + 2 * ty + rr;
        if (gm >= M) continue;
        float2* accp = rr ? acc1 : acc0;
        float2* cp = (float2*)(C + (size_t)gm * D);
        if (MODE == 0) {
#pragma unroll
            for (int j = 0; j < 25; j++) cp[tx * 25 + j] = accp[j];
        } else {
            int sI = ei[gm];
            int ev = et[gm];
            const float2* xr = (const float2*)(x + (size_t)sI * D);
            const float2* rv = (const float2*)(rel + (size_t)ev * D);
#pragma unroll
            for (int j = 0; j < 25; j++) {
                int c2 = tx * 25 + j;
                float2 q = accp[j], rl = rv[c2], xx = xr[c2];
                float2 o;
                o.x = xx.x * (0.5f * rl.x + 0.5f * q.x);
                o.y = xx.y * (0.5f * rl.y + 0.5f * q.y);
                cp[c2] = o;
            }
        }
    }
}

// ---------------- per-dst CSR aggregation of norm*P (both sides) ----------------
constexpr int AGG_BLOCKS = 400, ROWS_PB = NE / AGG_BLOCKS;  // 100 rows/block
__global__ void aggregate_k(const float* __restrict__ Pm, const float* __restrict__ nrm,
                            const int* __restrict__ off_in, const int* __restrict__ ce_in,
                            const int* __restrict__ off_out, const int* __restrict__ ce_out,
                            float* __restrict__ Min, float* __restrict__ Mout) {
    int f2 = threadIdx.x;
    if (f2 >= D / 2) return;
    int rbeg = blockIdx.x * ROWS_PB;
    for (int r = rbeg; r < rbeg + ROWS_PB; r++) {
        float2 vi = make_float2(0.f, 0.f);
        int j0 = off_in[r], j1 = off_in[r + 1];
        for (int j = j0; j < j1; j++) {
            int e = ce_in[j];
            float nm = nrm[e];
            float2 m = ((const float2*)(Pm + (size_t)e * D))[f2];
            vi.x += nm * m.x;
            vi.y += nm * m.y;
        }
        ((float2*)(Min + (size_t)r * D))[f2] = vi;

        float2 vo = make_float2(0.f, 0.f);
        j0 = off_out[r]; j1 = off_out[r + 1];
        for (int j = j0; j < j1; j++) {
            int e = ce_out[j];
            float nm = nrm[e];
            float2 m = ((const float2*)(Pm + (size_t)e * D))[f2];
            vo.x += nm * m.x;
            vo.y += nm * m.y;
        }
        ((float2*)(Mout + (size_t)r * D))[f2] = vo;
    }
}

// ---------------- BN stats / finalize / apply ----------------
__global__ void bn_stats_k(const float* __restrict__ t, float* __restrict__ sum,
                           float* __restrict__ sumsq) {
    int f = threadIdx.x;
    if (f >= D) return;
    int r0 = blockIdx.x * 250;
    float s = 0.f, ss = 0.f;
    for (int r = r0; r < r0 + 250; r++) {
        float v = t[(size_t)r * D + f];
        s += v; ss += v * v;
    }
    atomicAdd(&sum[f], s);
    atomicAdd(&sumsq[f], ss);
}

__global__ void bn_final_k(const float* __restrict__ sum, const float* __restrict__ sumsq,
                           const float* __restrict__ gamma, const float* __restrict__ beta,
                           float* __restrict__ cA, float* __restrict__ cB) {
    int f = threadIdx.x;
    if (f >= D) return;
    float mean = sum[f] * (1.f / NE);
    float var  = sumsq[f] * (1.f / NE) - mean * mean;
    if (var < 0.f) var = 0.f;
    float rs = rsqrtf(var * (1.f / 9.f) + EPSV);
    float a  = gamma[f] * rs * (1.f / 3.f);
    cA[f] = a;
    cB[f] = beta[f] - a * mean;
}

__global__ void bn_apply_k(const float* __restrict__ t, const float* __restrict__ cA,
                           const float* __restrict__ cB, float* __restrict__ xo) {
    int i = blockIdx.x * blockDim.x + threadIdx.x;
    if (i < NE * D / 2) {
        int f2 = i % (D / 2);
        float2 v = ((const float2*)t)[i];
        float2 o;
        o.x = tanhf(cA[2 * f2] * v.x + cB[2 * f2]);
        o.y = tanhf(cA[2 * f2 + 1] * v.y + cB[2 * f2 + 1]);
        ((float2*)xo)[i] = o;
    }
}

// ---------------- output gathers ----------------
__global__ void gather_k(const float* __restrict__ src, const int* __restrict__ idx,
                         float* __restrict__ out) {
    int b = blockIdx.x;
    int f = threadIdx.x;
    if (f < D / 2) {
        ((float2*)(out + (size_t)b * D))[f] =
            ((const float2*)(src + (size_t)idx[b] * D))[f];
    }
}

// ---------------- driver ----------------
extern "C" void kernel_launch(void* const* d_in, const int* in_sizes, int n_in,
                              void* d_out, int out_size) {
    const int* ei  = (const int*)d_in[0];
    const int* et  = (const int*)d_in[1];
    const int* qe  = (const int*)d_in[2];
    const int* qr  = (const int*)d_in[3];
    const int* sub = (const int*)d_in[4];
    const int* rel = (const int*)d_in[5];
    const float* init_embed = (const float*)d_in[6];
    const float* init_rel   = (const float*)d_in[7];
    const float* L[2][9];
    for (int l = 0; l < 2; l++)
        for (int p = 0; p < 9; p++) L[l][p] = (const float*)d_in[8 + l * 9 + p];

    float *deg, *nrm, *relbuf, *r1, *r2, *Bcat, *Q, *P, *Min, *Mout, *agg, *x1;
    float *sum, *sumsq, *cA, *cB;
    int *cin, *cout, *oin, *oout, *curin, *curout, *cein, *ceout;
    cudaGetSymbolAddress((void**)&deg,    g_deg);
    cudaGetSymbolAddress((void**)&nrm,    g_norm);
    cudaGetSymbolAddress((void**)&cin,    g_cnt_in);
    cudaGetSymbolAddress((void**)&cout,   g_cnt_out);
    cudaGetSymbolAddress((void**)&oin,    g_off_in);
    cudaGetSymbolAddress((void**)&oout,   g_off_out);
    cudaGetSymbolAddress((void**)&curin,  g_cur_in);
    cudaGetSymbolAddress((void**)&curout, g_cur_out);
    cudaGetSymbolAddress((void**)&cein,   g_ce_in);
    cudaGetSymbolAddress((void**)&ceout,  g_ce_out);
    cudaGetSymbolAddress((void**)&relbuf, g_relbuf);
    cudaGetSymbolAddress((void**)&r1,     g_r1);
    cudaGetSymbolAddress((void**)&r2,     g_r2);
    cudaGetSymbolAddress((void**)&Bcat,   g_Bcat);
    cudaGetSymbolAddress((void**)&Q,      g_Q);
    cudaGetSymbolAddress((void**)&P,      g_P);
    cudaGetSymbolAddress((void**)&Min,    g_Min);
    cudaGetSymbolAddress((void**)&Mout,   g_Mout);
    cudaGetSymbolAddress((void**)&agg,    g_agg);
    cudaGetSymbolAddress((void**)&x1,     g_x1);
    cudaGetSymbolAddress((void**)&sum,    g_sum);
    cudaGetSymbolAddress((void**)&sumsq,  g_sumsq);
    cudaGetSymbolAddress((void**)&cA,     g_cA);
    cudaGetSymbolAddress((void**)&cB,     g_cB);

    float* out     = (float*)d_out;
    float* out_sub = out;
    float* out_rel = out + NB * D;
    float* out_x   = out + 2 * NB * D;

    // graph structure (layer-invariant)
    cudaMemsetAsync(deg, 0, 2 * NE * sizeof(float));
    cudaMemsetAsync(cin, 0, NE * sizeof(int));
    cudaMemsetAsync(cout, 0, NE * sizeof(int));
    degcnt_k<<<(TOT + 255) / 256, 256>>>(ei, deg, cin, cout);
    norm_k<<<(TOT + 255) / 256, 256>>>(ei, deg, nrm);
    scan_k<<<1, SCAN_T>>>(cin, oin, curin, EHALF);
    scan_k<<<1, SCAN_T>>>(cout, oout, curout, EHALF);
    fill_k<<<(TOT + 255) / 256, 256>>>(ei, curin, curout, cein, ceout);

    for (int l = 0; l < 2; l++) {
        const float* x_in = l ? x1 : init_embed;
        const float* r_in = l ? r1 : init_rel;
        float* x_out = l ? out_x : x1;
        float* r_out = l ? r2 : r1;

        cudaMemcpyAsync(relbuf, r_in, R2 * D * sizeof(float), cudaMemcpyDeviceToDevice);
        cudaMemcpyAsync(relbuf + R2 * D, L[l][5], D * sizeof(float), cudaMemcpyDeviceToDevice);
        cudaMemsetAsync(sum, 0, D * sizeof(float));
        cudaMemsetAsync(sumsq, 0, D * sizeof(float));

        prep_bcat_k<<<(3 * D * D + 255) / 256, 256>>>(L[l][1], L[l][2], L[l][0], L[l][5], Bcat);
        build_q_k<<<TOT, 128>>>(x_in, relbuf, qe, qr, Q);
        // qual GEMM + fused P construction
        gemm_k<1, 1><<<TOT / BM, NT>>>(Q, nullptr, nullptr, L[l][4], P, TOT,
                                       ei, et, x_in, relbuf);
        // per-dst aggregation of norm*P
        aggregate_k<<<AGG_BLOCKS, 128>>>(P, nrm, oin, cein, oout, ceout, Min, Mout);
        // combined K=600 GEMM: agg = Min@w_in + Mout@w_out + x@(diag(lr)w_loop)
        gemm_k<0, 3><<<(NE + BM - 1) / BM, NT>>>(Min, Mout, x_in, Bcat, agg, NE,
                                                 nullptr, nullptr, nullptr, nullptr);
        // BN + tanh
        bn_stats_k<<<NE / 250, 224>>>(agg, sum, sumsq);
        bn_final_k<<<1, 224>>>(sum, sumsq, L[l][7], L[l][8], cA, cB);
        bn_apply_k<<<(NE * D / 2 + 255) / 256, 256>>>(agg, cA, cB, x_out);
        // rel update
        gemm_k<0, 1><<<(R2 + BM - 1) / BM, NT>>>(r_in, nullptr, nullptr, L[l][3],
                                                 r_out, R2, nullptr, nullptr,
                                                 nullptr, nullptr);
    }

    gather_k<<<NB, 128>>>(out_x, sub, out_sub);
    gather_k<<<NB, 128>>>(r2, rel, out_rel);
}

// round 5
// speedup vs baseline: 1.2343x; 1.2343x over previous
#include <cuda_runtime.h>
#include <math.h>
#include <stdint.h>

#define D      200
#define NE     40000
#define TOT    160000
#define EHALF  80000
#define R2     200
#define NB     1024
#define EPSV   1e-5f

// ---------------- scratch (static device globals; no allocation) ----------------
__device__ float g_deg[2 * NE];
__device__ float g_norm[TOT];
__device__ int   g_cnt_in[NE], g_cnt_out[NE];
__device__ int   g_off_in[NE + 1], g_off_out[NE + 1];
__device__ int   g_cur_in[NE], g_cur_out[NE];
__device__ int   g_ce_in[EHALF], g_ce_out[EHALF];
__device__ float g_relbuf[(R2 + 1) * D];
__device__ float g_r1[R2 * D];
__device__ float g_r2[R2 * D];
__device__ float g_Bcat[3 * D * D];
__device__ float g_Q[(size_t)TOT * D];
__device__ float g_P[(size_t)TOT * D];
__device__ float g_Min[NE * D];
__device__ float g_Mout[NE * D];
__device__ float g_agg[NE * D];
__device__ float g_x1[NE * D];
__device__ float g_sum[D], g_sumsq[D], g_cA[D], g_cB[D];

// packed f32x2 FMA (sm_103a FFMA2 — PTX only)
__device__ __forceinline__ void fma2(float2& c, float2 a, float2 b) {
    unsigned long long cc = *reinterpret_cast<const unsigned long long*>(&c);
    unsigned long long aa = *reinterpret_cast<const unsigned long long*>(&a);
    unsigned long long bb = *reinterpret_cast<const unsigned long long*>(&b);
    asm("fma.rn.f32x2 %0, %1, %2, %0;" : "+l"(cc) : "l"(aa), "l"(bb));
    c = *reinterpret_cast<float2*>(&cc);
}

// ---------------- degree + per-side dst counts ----------------
__global__ void degcnt_k(const int* __restrict__ ei, float* __restrict__ deg,
                         int* __restrict__ cin, int* __restrict__ cout) {
    int i = blockIdx.x * blockDim.x + threadIdx.x;
    if (i < TOT) {
        int off = (i >= EHALF) ? NE : 0;
        atomicAdd(&deg[off + ei[i]], 1.0f);
        int dst = ei[TOT + i];
        if (i < EHALF) atomicAdd(&cin[dst], 1);
        else           atomicAdd(&cout[dst], 1);
    }
}

__global__ void norm_k(const int* __restrict__ ei, const float* __restrict__ deg,
                       float* __restrict__ nrm) {
    int i = blockIdx.x * blockDim.x + threadIdx.x;
    if (i < TOT) {
        int off = (i >= EHALF) ? NE : 0;
        float a = deg[off + ei[i]];
        float b = deg[off + ei[TOT + i]];
        float va = (a > 0.f) ? rsqrtf(a) : 0.f;
        float vb = (b > 0.f) ? rsqrtf(b) : 0.f;
        nrm[i] = va * vb;
    }
}

// ---------------- CSR scan + fill ----------------
#define SCAN_T 1024
__global__ void scan_k(const int* __restrict__ cnt, int* __restrict__ off,
                       int* __restrict__ cur, int total) {
    __shared__ int part[SCAN_T];
    int t = threadIdx.x;
    const int CH = (NE + SCAN_T - 1) / SCAN_T;
    int base = t * CH;
    int s = 0;
    for (int i = 0; i < CH; i++) {
        int idx = base + i;
        if (idx < NE) s += cnt[idx];
    }
    part[t] = s;
    __syncthreads();
    for (int d = 1; d < SCAN_T; d <<= 1) {
        int v = (t >= d) ? part[t - d] : 0;
        __syncthreads();
        part[t] += v;
        __syncthreads();
    }
    int run = (t > 0) ? part[t - 1] : 0;
    for (int i = 0; i < CH; i++) {
        int idx = base + i;
        if (idx < NE) {
            off[idx] = run;
            cur[idx] = run;
            run += cnt[idx];
        }
    }
    if (t == SCAN_T - 1) off[NE] = total;
}

__global__ void fill_k(const int* __restrict__ ei, int* __restrict__ cur_in,
                       int* __restrict__ cur_out, int* __restrict__ ce_in,
                       int* __restrict__ ce_out) {
    int e = blockIdx.x * blockDim.x + threadIdx.x;
    if (e < TOT) {
        int dst = ei[TOT + e];
        if (e < EHALF) { int p = atomicAdd(&cur_in[dst], 1);  ce_in[p] = e; }
        else           { int p = atomicAdd(&cur_out[dst], 1); ce_out[p] = e; }
    }
}

// ---------------- Bcat = [w_in ; w_out ; diag(loop_rel)@w_loop] ----------------
__global__ void prep_bcat_k(const float* __restrict__ w_in, const float* __restrict__ w_out,
                            const float* __restrict__ w_loop, const float* __restrict__ lr,
                            float* __restrict__ Bc) {
    int i = blockIdx.x * blockDim.x + threadIdx.x;
    if (i >= 3 * D * D) return;
    int r = i / D, c = i - r * D;
    float v;
    if (r < D)            v = w_in[r * D + c];
    else if (r < 2 * D)   v = w_out[(r - D) * D + c];
    else                  v = lr[r - 2 * D] * w_loop[(r - 2 * D) * D + c];
    Bc[i] = v;
}

// ---------------- qualifier feature build (float2) ----------------
__global__ void build_q_k(const float* __restrict__ x, const float* __restrict__ rel,
                          const int* __restrict__ qe, const int* __restrict__ qr,
                          float* __restrict__ Q) {
    int e = blockIdx.x;
    int f = threadIdx.x;
    if (f >= D / 2) return;
    int e0 = qe[e], e1 = qe[TOT + e];
    int r0 = qr[e], r1 = qr[TOT + e];
    float2 a = ((const float2*)(x + (size_t)e0 * D))[f];
    float2 b = ((const float2*)(rel + (size_t)r0 * D))[f];
    float2 c = ((const float2*)(x + (size_t)e1 * D))[f];
    float2 d = ((const float2*)(rel + (size_t)r1 * D))[f];
    float2 o;
    o.x = a.x * b.x + c.x * d.x;
    o.y = a.y * b.y + c.y * d.y;
    ((float2*)(Q + (size_t)e * D))[f] = o;
}

// ---------------- cp.async pipelined FFMA2 GEMM (R3 microkernel + segmented A) ----------------
// MODE 0: C[gm] = acc (plain store)
// MODE 1: C[gm] = x[ei[gm]] * (0.5*rel[et[gm]] + 0.5*acc)
constexpr int BM = 128, BK = 10, NT = 256, NSTG = 3;

template <int MODE, int NSEG>
__global__ __launch_bounds__(NT, 2)
void gemm_k(const float* A0, const float* A1, const float* A2,
            const float* __restrict__ Bw, float* C, int M,
            const int* __restrict__ ei, const int* __restrict__ et,
            const float* __restrict__ x, const float* __restrict__ rel) {
    __shared__ __align__(16) float As[NSTG][BM * BK];
    __shared__ __align__(16) float Bs[NSTG][BK * D];

    const int t  = threadIdx.x;
    const int tx = t & 3;        // float2-col group 0..3
    const int ty = t >> 2;       // row pair 0..63
    const int m0 = blockIdx.x * BM;
    constexpr int NIT = NSEG * (D / BK);

    uint32_t sA = (uint32_t)__cvta_generic_to_shared(&As[0][0]);
    uint32_t sB = (uint32_t)__cvta_generic_to_shared(&Bs[0][0]);

    auto issue_tile = [&](int tile) {
        int s = tile % NSTG;
        int seg = (NSEG == 1) ? 0 : tile / (D / BK);
        int k0 = tile * BK - seg * D;              // col within segment
        const float* Ause = (NSEG == 1) ? A0
                           : (seg == 0 ? A0 : (seg == 1 ? A1 : A2));
        for (int i = t; i < BM * BK / 2; i += NT) {     // 640 8B chunks
            int r = i / 5, cc = i - r * 5;
            int gm = m0 + r;
            const float* src = Ause + (size_t)gm * D + k0 + cc * 2;
            int sz = (gm < M) ? 8 : 0;
            asm volatile("cp.async.ca.shared.global [%0], [%1], 8, %2;\n"
                         :: "r"(sA + (uint32_t)((s * BM * BK + r * BK + cc * 2) * 4)),
                            "l"(src), "r"(sz));
        }
        int kb = tile * BK;                             // row in Bcat (global K)
        for (int i = t; i < BK * D / 4; i += NT) {      // 500 16B chunks
            int rr = i / 50, cc = i - rr * 50;
            const float* src = Bw + (size_t)(kb + rr) * D + cc * 4;
            asm volatile("cp.async.ca.shared.global [%0], [%1], 16;\n"
                         :: "r"(sB + (uint32_t)((s * BK * D + rr * D + cc * 4) * 4)),
                            "l"(src));
        }
        asm volatile("cp.async.commit_group;\n");
    };

    issue_tile(0);
    issue_tile(1);

    float2 acc0[25], acc1[25];
#pragma unroll
    for (int j = 0; j < 25; j++) {
        acc0[j] = make_float2(0.f, 0.f);
        acc1[j] = make_float2(0.f, 0.f);
    }

    const int r0 = 2 * ty * BK, r1 = (2 * ty + 1) * BK;
    for (int it = 0; it < NIT; it++) {
        asm volatile("cp.async.wait_group 1;\n");
        __syncthreads();
        const float* as = &As[it % NSTG][0];
        const float* bs = &Bs[it % NSTG][0];
#pragma unroll
        for (int kk = 0; kk < BK; kk += 2) {
            float2 a0 = *(const float2*)(as + r0 + kk);
            float2 a1 = *(const float2*)(as + r1 + kk);
            float2 a00 = make_float2(a0.x, a0.x), a01 = make_float2(a0.y, a0.y);
            float2 a10 = make_float2(a1.x, a1.x), a11 = make_float2(a1.y, a1.y);
            const float2* b0 = (const float2*)(bs + kk * D);
            const float2* b1 = (const float2*)(bs + (kk + 1) * D);
#pragma unroll
            for (int j = 0; j < 25; j++) {
                float2 bv0 = b0[tx + 4 * j];
                float2 bv1 = b1[tx + 4 * j];
                fma2(acc0[j], a00, bv0);
                fma2(acc1[j], a10, bv0);
                fma2(acc0[j], a01, bv1);
                fma2(acc1[j], a11, bv1);
            }
        }
        __syncthreads();
        if (it + 2 < NIT) issue_tile(it + 2);
        else asm volatile("cp.async.commit_group;\n");
    }

#pragma unroll
    for (int rr = 0; rr < 2; rr++) {
        int gm = m0 + 2 * ty + rr;
        if (gm >= M) continue;
        float2* accp = rr ? acc1 : acc0;
        float2* cp = (float2*)(C + (size_t)gm * D);
        if (MODE == 0) {
#pragma unroll
            for (int j = 0; j < 25; j++) cp[tx + 4 * j] = accp[j];
        } else {
            int sI = ei[gm];
            int ev = et[gm];
            const float2* xr = (const float2*)(x + (size_t)sI * D);
            const float2* rv = (const float2*)(rel + (size_t)ev * D);
#pragma unroll
            for (int j = 0; j < 25; j++) {
                int c2 = tx + 4 * j;
                float2 q = accp[j], rl = rv[c2], xx = xr[c2];
                float2 o;
                o.x = xx.x * (0.5f * rl.x + 0.5f * q.x);
                o.y = xx.y * (0.5f * rl.y + 0.5f * q.y);
                cp[c2] = o;
            }
        }
    }
}

// ---------------- per-dst CSR aggregation of norm*P (both sides) ----------------
constexpr int AGG_BLOCKS = 400, ROWS_PB = NE / AGG_BLOCKS;  // 100 rows/block
__global__ void aggregate_k(const float* __restrict__ Pm, const float* __restrict__ nrm,
                            const int* __restrict__ off_in, const int* __restrict__ ce_in,
                            const int* __restrict__ off_out, const int* __restrict__ ce_out,
                            float* __restrict__ Min, float* __restrict__ Mout) {
    int f2 = threadIdx.x;
    if (f2 >= D / 2) return;
    int rbeg = blockIdx.x * ROWS_PB;
    for (int r = rbeg; r < rbeg + ROWS_PB; r++) {
        float2 vi = make_float2(0.f, 0.f);
        int j0 = off_in[r], j1 = off_in[r + 1];
        for (int j = j0; j < j1; j++) {
            int e = ce_in[j];
            float nm = nrm[e];
            float2 m = ((const float2*)(Pm + (size_t)e * D))[f2];
            vi.x += nm * m.x;
            vi.y += nm * m.y;
        }
        ((float2*)(Min + (size_t)r * D))[f2] = vi;

        float2 vo = make_float2(0.f, 0.f);
        j0 = off_out[r]; j1 = off_out[r + 1];
        for (int j = j0; j < j1; j++) {
            int e = ce_out[j];
            float nm = nrm[e];
            float2 m = ((const float2*)(Pm + (size_t)e * D))[f2];
            vo.x += nm * m.x;
            vo.y += nm * m.y;
        }
        ((float2*)(Mout + (size_t)r * D))[f2] = vo;
    }
}

// ---------------- BN stats / finalize / apply ----------------
__global__ void bn_stats_k(const float* __restrict__ t, float* __restrict__ sum,
                           float* __restrict__ sumsq) {
    int f = threadIdx.x;
    if (f >= D) return;
    int r0 = blockIdx.x * 250;
    float s = 0.f, ss = 0.f;
    for (int r = r0; r < r0 + 250; r++) {
        float v = t[(size_t)r * D + f];
        s += v; ss += v * v;
    }
    atomicAdd(&sum[f], s);
    atomicAdd(&sumsq[f], ss);
}

__global__ void bn_final_k(const float* __restrict__ sum, const float* __restrict__ sumsq,
                           const float* __restrict__ gamma, const float* __restrict__ beta,
                           float* __restrict__ cA, float* __restrict__ cB) {
    int f = threadIdx.x;
    if (f >= D) return;
    float mean = sum[f] * (1.f / NE);
    float var  = sumsq[f] * (1.f / NE) - mean * mean;
    if (var < 0.f) var = 0.f;
    float rs = rsqrtf(var * (1.f / 9.f) + EPSV);
    float a  = gamma[f] * rs * (1.f / 3.f);
    cA[f] = a;
    cB[f] = beta[f] - a * mean;
}

__global__ void bn_apply_k(const float* __restrict__ t, const float* __restrict__ cA,
                           const float* __restrict__ cB, float* __restrict__ xo) {
    int i = blockIdx.x * blockDim.x + threadIdx.x;
    if (i < NE * D / 2) {
        int f2 = i % (D / 2);
        float2 v = ((const float2*)t)[i];
        float2 o;
        o.x = tanhf(cA[2 * f2] * v.x + cB[2 * f2]);
        o.y = tanhf(cA[2 * f2 + 1] * v.y + cB[2 * f2 + 1]);
        ((float2*)xo)[i] = o;
    }
}

// ---------------- output gathers ----------------
__global__ void gather_k(const float* __restrict__ src, const int* __restrict__ idx,
                         float* __restrict__ out) {
    int b = blockIdx.x;
    int f = threadIdx.x;
    if (f < D / 2) {
        ((float2*)(out + (size_t)b * D))[f] =
            ((const float2*)(src + (size_t)idx[b] * D))[f];
    }
}

// ---------------- driver ----------------
extern "C" void kernel_launch(void* const* d_in, const int* in_sizes, int n_in,
                              void* d_out, int out_size) {
    const int* ei  = (const int*)d_in[0];
    const int* et  = (const int*)d_in[1];
    const int* qe  = (const int*)d_in[2];
    const int* qr  = (const int*)d_in[3];
    const int* sub = (const int*)d_in[4];
    const int* rel = (const int*)d_in[5];
    const float* init_embed = (const float*)d_in[6];
    const float* init_rel   = (const float*)d_in[7];
    const float* L[2][9];
    for (int l = 0; l < 2; l++)
        for (int p = 0; p < 9; p++) L[l][p] = (const float*)d_in[8 + l * 9 + p];

    float *deg, *nrm, *relbuf, *r1, *r2, *Bcat, *Q, *P, *Min, *Mout, *agg, *x1;
    float *sum, *sumsq, *cA, *cB;
    int *cin, *cout, *oin, *oout, *curin, *curout, *cein, *ceout;
    cudaGetSymbolAddress((void**)&deg,    g_deg);
    cudaGetSymbolAddress((void**)&nrm,    g_norm);
    cudaGetSymbolAddress((void**)&cin,    g_cnt_in);
    cudaGetSymbolAddress((void**)&cout,   g_cnt_out);
    cudaGetSymbolAddress((void**)&oin,    g_off_in);
    cudaGetSymbolAddress((void**)&oout,   g_off_out);
    cudaGetSymbolAddress((void**)&curin,  g_cur_in);
    cudaGetSymbolAddress((void**)&curout, g_cur_out);
    cudaGetSymbolAddress((void**)&cein,   g_ce_in);
    cudaGetSymbolAddress((void**)&ceout,  g_ce_out);
    cudaGetSymbolAddress((void**)&relbuf, g_relbuf);
    cudaGetSymbolAddress((void**)&r1,     g_r1);
    cudaGetSymbolAddress((void**)&r2,     g_r2);
    cudaGetSymbolAddress((void**)&Bcat,   g_Bcat);
    cudaGetSymbolAddress((void**)&Q,      g_Q);
    cudaGetSymbolAddress((void**)&P,      g_P);
    cudaGetSymbolAddress((void**)&Min,    g_Min);
    cudaGetSymbolAddress((void**)&Mout,   g_Mout);
    cudaGetSymbolAddress((void**)&agg,    g_agg);
    cudaGetSymbolAddress((void**)&x1,     g_x1);
    cudaGetSymbolAddress((void**)&sum,    g_sum);
    cudaGetSymbolAddress((void**)&sumsq,  g_sumsq);
    cudaGetSymbolAddress((void**)&cA,     g_cA);
    cudaGetSymbolAddress((void**)&cB,     g_cB);

    float* out     = (float*)d_out;
    float* out_sub = out;
    float* out_rel = out + NB * D;
    float* out_x   = out + 2 * NB * D;

    // graph structure (layer-invariant)
    cudaMemsetAsync(deg, 0, 2 * NE * sizeof(float));
    cudaMemsetAsync(cin, 0, NE * sizeof(int));
    cudaMemsetAsync(cout, 0, NE * sizeof(int));
    degcnt_k<<<(TOT + 255) / 256, 256>>>(ei, deg, cin, cout);
    norm_k<<<(TOT + 255) / 256, 256>>>(ei, deg, nrm);
    scan_k<<<1, SCAN_T>>>(cin, oin, curin, EHALF);
    scan_k<<<1, SCAN_T>>>(cout, oout, curout, EHALF);
    fill_k<<<(TOT + 255) / 256, 256>>>(ei, curin, curout, cein, ceout);

    for (int l = 0; l < 2; l++) {
        const float* x_in = l ? x1 : init_embed;
        const float* r_in = l ? r1 : init_rel;
        float* x_out = l ? out_x : x1;
        float* r_out = l ? r2 : r1;

        cudaMemcpyAsync(relbuf, r_in, R2 * D * sizeof(float), cudaMemcpyDeviceToDevice);
        cudaMemcpyAsync(relbuf + R2 * D, L[l][5], D * sizeof(float), cudaMemcpyDeviceToDevice);
        cudaMemsetAsync(sum, 0, D * sizeof(float));
        cudaMemsetAsync(sumsq, 0, D * sizeof(float));

        prep_bcat_k<<<(3 * D * D + 255) / 256, 256>>>(L[l][1], L[l][2], L[l][0], L[l][5], Bcat);
        build_q_k<<<TOT, 128>>>(x_in, relbuf, qe, qr, Q);
        // qual GEMM + fused P construction
        gemm_k<1, 1><<<TOT / BM, NT>>>(Q, nullptr, nullptr, L[l][4], P, TOT,
                                       ei, et, x_in, relbuf);
        // per-dst aggregation of norm*P
        aggregate_k<<<AGG_BLOCKS, 128>>>(P, nrm, oin, cein, oout, ceout, Min, Mout);
        // combined K=600 GEMM: agg = Min@w_in + Mout@w_out + x@(diag(lr)w_loop)
        gemm_k<0, 3><<<(NE + BM - 1) / BM, NT>>>(Min, Mout, x_in, Bcat, agg, NE,
                                                 nullptr, nullptr, nullptr, nullptr);
        // BN + tanh
        bn_stats_k<<<NE / 250, 224>>>(agg, sum, sumsq);
        bn_final_k<<<1, 224>>>(sum, sumsq, L[l][7], L[l][8], cA, cB);
        bn_apply_k<<<(NE * D / 2 + 255) / 256, 256>>>(agg, cA, cB, x_out);
        // rel update
        gemm_k<0, 1><<<(R2 + BM - 1) / BM, NT>>>(r_in, nullptr, nullptr, L[l][3],
                                                 r_out, R2, nullptr, nullptr,
                                                 nullptr, nullptr);
    }

    gather_k<<<NB, 128>>>(out_x, sub, out_sub);
    gather_k<<<NB, 128>>>(r2, rel, out_rel);
}

// round 6
// speedup vs baseline: 1.2783x; 1.0357x over previous
#include <cuda_runtime.h>
#include <math.h>
#include <stdint.h>

#define D      200
#define NE     40000
#define TOT    160000
#define EHALF  80000
#define R2     200
#define NB     1024
#define EPSV   1e-5f

// ---------------- scratch (static device globals; no allocation) ----------------
__device__ float g_deg[2 * NE];
__device__ float g_norm[TOT];
__device__ int   g_cnt_in[NE], g_cnt_out[NE];
__device__ int   g_off_in[NE + 1], g_off_out[NE + 1];
__device__ int   g_cur_in[NE], g_cur_out[NE];
__device__ int   g_ce_in[EHALF], g_ce_out[EHALF];
__device__ float g_relbuf[(R2 + 1) * D];
__device__ float g_r1[R2 * D];
__device__ float g_r2[R2 * D];
__device__ float g_Bcat[3 * D * D];
__device__ float g_Q[(size_t)TOT * D];
__device__ float g_P[(size_t)TOT * D];
__device__ float g_Min[NE * D];
__device__ float g_Mout[NE * D];
__device__ float g_agg[NE * D];
__device__ float g_x1[NE * D];
__device__ float g_sum[D], g_sumsq[D], g_cA[D], g_cB[D];

// packed f32x2 FMA (sm_103a FFMA2 — PTX only)
__device__ __forceinline__ void fma2(float2& c, float2 a, float2 b) {
    unsigned long long cc = *reinterpret_cast<const unsigned long long*>(&c);
    unsigned long long aa = *reinterpret_cast<const unsigned long long*>(&a);
    unsigned long long bb = *reinterpret_cast<const unsigned long long*>(&b);
    asm("fma.rn.f32x2 %0, %1, %2, %0;" : "+l"(cc) : "l"(aa), "l"(bb));
    c = *reinterpret_cast<float2*>(&cc);
}

// ---------------- degree + per-side dst counts ----------------
__global__ void degcnt_k(const int* __restrict__ ei, float* __restrict__ deg,
                         int* __restrict__ cin, int* __restrict__ cout) {
    int i = blockIdx.x * blockDim.x + threadIdx.x;
    if (i < TOT) {
        int off = (i >= EHALF) ? NE : 0;
        atomicAdd(&deg[off + ei[i]], 1.0f);
        int dst = ei[TOT + i];
        if (i < EHALF) atomicAdd(&cin[dst], 1);
        else           atomicAdd(&cout[dst], 1);
    }
}

__global__ void norm_k(const int* __restrict__ ei, const float* __restrict__ deg,
                       float* __restrict__ nrm) {
    int i = blockIdx.x * blockDim.x + threadIdx.x;
    if (i < TOT) {
        int off = (i >= EHALF) ? NE : 0;
        float a = deg[off + ei[i]];
        float b = deg[off + ei[TOT + i]];
        float va = (a > 0.f) ? rsqrtf(a) : 0.f;
        float vb = (b > 0.f) ? rsqrtf(b) : 0.f;
        nrm[i] = va * vb;
    }
}

// ---------------- CSR scan + fill ----------------
#define SCAN_T 1024
__global__ void scan_k(const int* __restrict__ cnt, int* __restrict__ off,
                       int* __restrict__ cur, int total) {
    __shared__ int part[SCAN_T];
    int t = threadIdx.x;
    const int CH = (NE + SCAN_T - 1) / SCAN_T;
    int base = t * CH;
    int s = 0;
    for (int i = 0; i < CH; i++) {
        int idx = base + i;
        if (idx < NE) s += cnt[idx];
    }
    part[t] = s;
    __syncthreads();
    for (int d = 1; d < SCAN_T; d <<= 1) {
        int v = (t >= d) ? part[t - d] : 0;
        __syncthreads();
        part[t] += v;
        __syncthreads();
    }
    int run = (t > 0) ? part[t - 1] : 0;
    for (int i = 0; i < CH; i++) {
        int idx = base + i;
        if (idx < NE) {
            off[idx] = run;
            cur[idx] = run;
            run += cnt[idx];
        }
    }
    if (t == SCAN_T - 1) off[NE] = total;
}

__global__ void fill_k(const int* __restrict__ ei, int* __restrict__ cur_in,
                       int* __restrict__ cur_out, int* __restrict__ ce_in,
                       int* __restrict__ ce_out) {
    int e = blockIdx.x * blockDim.x + threadIdx.x;
    if (e < TOT) {
        int dst = ei[TOT + e];
        if (e < EHALF) { int p = atomicAdd(&cur_in[dst], 1);  ce_in[p] = e; }
        else           { int p = atomicAdd(&cur_out[dst], 1); ce_out[p] = e; }
    }
}

// ---------------- Bcat = [w_in ; w_out ; diag(loop_rel)@w_loop] ----------------
__global__ void prep_bcat_k(const float* __restrict__ w_in, const float* __restrict__ w_out,
                            const float* __restrict__ w_loop, const float* __restrict__ lr,
                            float* __restrict__ Bc) {
    int i = blockIdx.x * blockDim.x + threadIdx.x;
    if (i >= 3 * D * D) return;
    int r = i / D, c = i - r * D;
    float v;
    if (r < D)            v = w_in[r * D + c];
    else if (r < 2 * D)   v = w_out[(r - D) * D + c];
    else                  v = lr[r - 2 * D] * w_loop[(r - 2 * D) * D + c];
    Bc[i] = v;
}

// ---------------- qualifier feature build (float2) ----------------
__global__ void build_q_k(const float* __restrict__ x, const float* __restrict__ rel,
                          const int* __restrict__ qe, const int* __restrict__ qr,
                          float* __restrict__ Q) {
    int e = blockIdx.x;
    int f = threadIdx.x;
    if (f >= D / 2) return;
    int e0 = qe[e], e1 = qe[TOT + e];
    int r0 = qr[e], r1 = qr[TOT + e];
    float2 a = ((const float2*)(x + (size_t)e0 * D))[f];
    float2 b = ((const float2*)(rel + (size_t)r0 * D))[f];
    float2 c = ((const float2*)(x + (size_t)e1 * D))[f];
    float2 d = ((const float2*)(rel + (size_t)r1 * D))[f];
    float2 o;
    o.x = a.x * b.x + c.x * d.x;
    o.y = a.y * b.y + c.y * d.y;
    ((float2*)(Q + (size_t)e * D))[f] = o;
}

// ---------------- cp.async pipelined FFMA2 GEMM (R3 microkernel + segmented A) ----------------
// MODE 0: C[gm] = acc (plain store)
// MODE 1: C[gm] = nrm[gm] * x[ei[gm]] * (0.5*rel[et[gm]] + 0.5*acc)
constexpr int BM = 128, BK = 10, NT = 256, NSTG = 3;

template <int MODE, int NSEG>
__global__ __launch_bounds__(NT, 2)
void gemm_k(const float* A0, const float* A1, const float* A2,
            const float* __restrict__ Bw, float* C, int M,
            const int* __restrict__ ei, const int* __restrict__ et,
            const float* __restrict__ x, const float* __restrict__ rel,
            const float* __restrict__ nrm) {
    __shared__ __align__(16) float As[NSTG][BM * BK];
    __shared__ __align__(16) float Bs[NSTG][BK * D];

    const int t  = threadIdx.x;
    const int tx = t & 3;        // float2-col group 0..3
    const int ty = t >> 2;       // row pair 0..63
    const int m0 = blockIdx.x * BM;
    constexpr int NIT = NSEG * (D / BK);

    uint32_t sA = (uint32_t)__cvta_generic_to_shared(&As[0][0]);
    uint32_t sB = (uint32_t)__cvta_generic_to_shared(&Bs[0][0]);

    auto issue_tile = [&](int tile) {
        int s = tile % NSTG;
        int seg = (NSEG == 1) ? 0 : tile / (D / BK);
        int k0 = tile * BK - seg * D;              // col within segment
        const float* Ause = (NSEG == 1) ? A0
                           : (seg == 0 ? A0 : (seg == 1 ? A1 : A2));
        for (int i = t; i < BM * BK / 2; i += NT) {     // 640 8B chunks
            int r = i / 5, cc = i - r * 5;
            int gm = m0 + r;
            const float* src = Ause + (size_t)gm * D + k0 + cc * 2;
            int sz = (gm < M) ? 8 : 0;
            asm volatile("cp.async.ca.shared.global [%0], [%1], 8, %2;\n"
                         :: "r"(sA + (uint32_t)((s * BM * BK + r * BK + cc * 2) * 4)),
                            "l"(src), "r"(sz));
        }
        int kb = tile * BK;                             // row in Bcat (global K)
        for (int i = t; i < BK * D / 4; i += NT) {      // 500 16B chunks
            int rr = i / 50, cc = i - rr * 50;
            const float* src = Bw + (size_t)(kb + rr) * D + cc * 4;
            asm volatile("cp.async.ca.shared.global [%0], [%1], 16;\n"
                         :: "r"(sB + (uint32_t)((s * BK * D + rr * D + cc * 4) * 4)),
                            "l"(src));
        }
        asm volatile("cp.async.commit_group;\n");
    };

    issue_tile(0);
    issue_tile(1);

    float2 acc0[25], acc1[25];
#pragma unroll
    for (int j = 0; j < 25; j++) {
        acc0[j] = make_float2(0.f, 0.f);
        acc1[j] = make_float2(0.f, 0.f);
    }

    const int r0 = 2 * ty * BK, r1 = (2 * ty + 1) * BK;
    for (int it = 0; it < NIT; it++) {
        asm volatile("cp.async.wait_group 1;\n");
        __syncthreads();
        const float* as = &As[it % NSTG][0];
        const float* bs = &Bs[it % NSTG][0];
#pragma unroll
        for (int kk = 0; kk < BK; kk += 2) {
            float2 a0 = *(const float2*)(as + r0 + kk);
            float2 a1 = *(const float2*)(as + r1 + kk);
            float2 a00 = make_float2(a0.x, a0.x), a01 = make_float2(a0.y, a0.y);
            float2 a10 = make_float2(a1.x, a1.x), a11 = make_float2(a1.y, a1.y);
            const float2* b0 = (const float2*)(bs + kk * D);
            const float2* b1 = (const float2*)(bs + (kk + 1) * D);
#pragma unroll
            for (int j = 0; j < 25; j++) {
                float2 bv0 = b0[tx + 4 * j];
                float2 bv1 = b1[tx + 4 * j];
                fma2(acc0[j], a00, bv0);
                fma2(acc1[j], a10, bv0);
                fma2(acc0[j], a01, bv1);
                fma2(acc1[j], a11, bv1);
            }
        }
        __syncthreads();
        if (it + 2 < NIT) issue_tile(it + 2);
        else asm volatile("cp.async.commit_group;\n");
    }

#pragma unroll
    for (int rr = 0; rr < 2; rr++) {
        int gm = m0 + 2 * ty + rr;
        if (gm >= M) continue;
        float2* accp = rr ? acc1 : acc0;
        float2* cp = (float2*)(C + (size_t)gm * D);
        if (MODE == 0) {
#pragma unroll
            for (int j = 0; j < 25; j++) cp[tx + 4 * j] = accp[j];
        } else {
            int sI = ei[gm];
            int ev = et[gm];
            float nm = nrm[gm];
            const float2* xr = (const float2*)(x + (size_t)sI * D);
            const float2* rv = (const float2*)(rel + (size_t)ev * D);
#pragma unroll
            for (int j = 0; j < 25; j++) {
                int c2 = tx + 4 * j;
                float2 q = accp[j], rl = rv[c2], xx = xr[c2];
                float2 o;
                o.x = nm * xx.x * (0.5f * rl.x + 0.5f * q.x);
                o.y = nm * xx.y * (0.5f * rl.y + 0.5f * q.y);
                cp[c2] = o;
            }
        }
    }
}

// ---------------- per-dst CSR segment-sum of P (norm pre-applied) ----------------
// grid = NE/2 blocks, 256 threads: tid/128 selects row within pair, tid%128 = col
constexpr int AGG_BLOCKS = NE / 2;   // 20000
__global__ __launch_bounds__(256)
void aggregate_k(const float* __restrict__ Pm,
                 const int* __restrict__ off_in, const int* __restrict__ ce_in,
                 const int* __restrict__ off_out, const int* __restrict__ ce_out,
                 float* __restrict__ Min, float* __restrict__ Mout) {
    int f2 = threadIdx.x & 127;
    if (f2 >= D / 2) return;
    int r = blockIdx.x * 2 + (threadIdx.x >> 7);

    float2 vi = make_float2(0.f, 0.f);
    int j0 = off_in[r], j1 = off_in[r + 1];
    for (int j = j0; j < j1; j++) {
        float2 m = ((const float2*)(Pm + (size_t)ce_in[j] * D))[f2];
        vi.x += m.x;
        vi.y += m.y;
    }
    ((float2*)(Min + (size_t)r * D))[f2] = vi;

    float2 vo = make_float2(0.f, 0.f);
    j0 = off_out[r]; j1 = off_out[r + 1];
    for (int j = j0; j < j1; j++) {
        float2 m = ((const float2*)(Pm + (size_t)ce_out[j] * D))[f2];
        vo.x += m.x;
        vo.y += m.y;
    }
    ((float2*)(Mout + (size_t)r * D))[f2] = vo;
}

// ---------------- BN stats / finalize / apply ----------------
constexpr int BN_BLOCKS = 1600, BN_ROWS = NE / BN_BLOCKS;  // 25 rows/block
__global__ __launch_bounds__(128)
void bn_stats_k(const float* __restrict__ t, float* __restrict__ sum,
                float* __restrict__ sumsq) {
    int f2 = threadIdx.x;
    if (f2 >= D / 2) return;
    int r0 = blockIdx.x * BN_ROWS;
    float sx = 0.f, sy = 0.f, qx = 0.f, qy = 0.f;
    for (int r = r0; r < r0 + BN_ROWS; r++) {
        float2 v = ((const float2*)(t + (size_t)r * D))[f2];
        sx += v.x; sy += v.y;
        qx += v.x * v.x; qy += v.y * v.y;
    }
    atomicAdd(&sum[2 * f2], sx);
    atomicAdd(&sum[2 * f2 + 1], sy);
    atomicAdd(&sumsq[2 * f2], qx);
    atomicAdd(&sumsq[2 * f2 + 1], qy);
}

__global__ void bn_final_k(const float* __restrict__ sum, const float* __restrict__ sumsq,
                           const float* __restrict__ gamma, const float* __restrict__ beta,
                           float* __restrict__ cA, float* __restrict__ cB) {
    int f = threadIdx.x;
    if (f >= D) return;
    float mean = sum[f] * (1.f / NE);
    float var  = sumsq[f] * (1.f / NE) - mean * mean;
    if (var < 0.f) var = 0.f;
    float rs = rsqrtf(var * (1.f / 9.f) + EPSV);
    float a  = gamma[f] * rs * (1.f / 3.f);
    cA[f] = a;
    cB[f] = beta[f] - a * mean;
}

__global__ void bn_apply_k(const float* __restrict__ t, const float* __restrict__ cA,
                           const float* __restrict__ cB, float* __restrict__ xo) {
    int i = blockIdx.x * blockDim.x + threadIdx.x;
    if (i < NE * D / 2) {
        int f2 = i % (D / 2);
        float2 v = ((const float2*)t)[i];
        float2 o;
        o.x = tanhf(cA[2 * f2] * v.x + cB[2 * f2]);
        o.y = tanhf(cA[2 * f2 + 1] * v.y + cB[2 * f2 + 1]);
        ((float2*)xo)[i] = o;
    }
}

// ---------------- output gathers ----------------
__global__ void gather_k(const float* __restrict__ src, const int* __restrict__ idx,
                         float* __restrict__ out) {
    int b = blockIdx.x;
    int f = threadIdx.x;
    if (f < D / 2) {
        ((float2*)(out + (size_t)b * D))[f] =
            ((const float2*)(src + (size_t)idx[b] * D))[f];
    }
}

// ---------------- driver ----------------
extern "C" void kernel_launch(void* const* d_in, const int* in_sizes, int n_in,
                              void* d_out, int out_size) {
    const int* ei  = (const int*)d_in[0];
    const int* et  = (const int*)d_in[1];
    const int* qe  = (const int*)d_in[2];
    const int* qr  = (const int*)d_in[3];
    const int* sub = (const int*)d_in[4];
    const int* rel = (const int*)d_in[5];
    const float* init_embed = (const float*)d_in[6];
    const float* init_rel   = (const float*)d_in[7];
    const float* L[2][9];
    for (int l = 0; l < 2; l++)
        for (int p = 0; p < 9; p++) L[l][p] = (const float*)d_in[8 + l * 9 + p];

    float *deg, *nrm, *relbuf, *r1, *r2, *Bcat, *Q, *P, *Min, *Mout, *agg, *x1;
    float *sum, *sumsq, *cA, *cB;
    int *cin, *cout, *oin, *oout, *curin, *curout, *cein, *ceout;
    cudaGetSymbolAddress((void**)&deg,    g_deg);
    cudaGetSymbolAddress((void**)&nrm,    g_norm);
    cudaGetSymbolAddress((void**)&cin,    g_cnt_in);
    cudaGetSymbolAddress((void**)&cout,   g_cnt_out);
    cudaGetSymbolAddress((void**)&oin,    g_off_in);
    cudaGetSymbolAddress((void**)&oout,   g_off_out);
    cudaGetSymbolAddress((void**)&curin,  g_cur_in);
    cudaGetSymbolAddress((void**)&curout, g_cur_out);
    cudaGetSymbolAddress((void**)&cein,   g_ce_in);
    cudaGetSymbolAddress((void**)&ceout,  g_ce_out);
    cudaGetSymbolAddress((void**)&relbuf, g_relbuf);
    cudaGetSymbolAddress((void**)&r1,     g_r1);
    cudaGetSymbolAddress((void**)&r2,     g_r2);
    cudaGetSymbolAddress((void**)&Bcat,   g_Bcat);
    cudaGetSymbolAddress((void**)&Q,      g_Q);
    cudaGetSymbolAddress((void**)&P,      g_P);
    cudaGetSymbolAddress((void**)&Min,    g_Min);
    cudaGetSymbolAddress((void**)&Mout,   g_Mout);
    cudaGetSymbolAddress((void**)&agg,    g_agg);
    cudaGetSymbolAddress((void**)&x1,     g_x1);
    cudaGetSymbolAddress((void**)&sum,    g_sum);
    cudaGetSymbolAddress((void**)&sumsq,  g_sumsq);
    cudaGetSymbolAddress((void**)&cA,     g_cA);
    cudaGetSymbolAddress((void**)&cB,     g_cB);

    float* out     = (float*)d_out;
    float* out_sub = out;
    float* out_rel = out + NB * D;
    float* out_x   = out + 2 * NB * D;

    // graph structure (layer-invariant)
    cudaMemsetAsync(deg, 0, 2 * NE * sizeof(float));
    cudaMemsetAsync(cin, 0, NE * sizeof(int));
    cudaMemsetAsync(cout, 0, NE * sizeof(int));
    degcnt_k<<<(TOT + 255) / 256, 256>>>(ei, deg, cin, cout);
    norm_k<<<(TOT + 255) / 256, 256>>>(ei, deg, nrm);
    scan_k<<<1, SCAN_T>>>(cin, oin, curin, EHALF);
    scan_k<<<1, SCAN_T>>>(cout, oout, curout, EHALF);
    fill_k<<<(TOT + 255) / 256, 256>>>(ei, curin, curout, cein, ceout);

    for (int l = 0; l < 2; l++) {
        const float* x_in = l ? x1 : init_embed;
        const float* r_in = l ? r1 : init_rel;
        float* x_out = l ? out_x : x1;
        float* r_out = l ? r2 : r1;

        cudaMemcpyAsync(relbuf, r_in, R2 * D * sizeof(float), cudaMemcpyDeviceToDevice);
        cudaMemcpyAsync(relbuf + R2 * D, L[l][5], D * sizeof(float), cudaMemcpyDeviceToDevice);
        cudaMemsetAsync(sum, 0, D * sizeof(float));
        cudaMemsetAsync(sumsq, 0, D * sizeof(float));

        prep_bcat_k<<<(3 * D * D + 255) / 256, 256>>>(L[l][1], L[l][2], L[l][0], L[l][5], Bcat);
        build_q_k<<<TOT, 128>>>(x_in, relbuf, qe, qr, Q);
        // qual GEMM + fused P construction (norm folded in)
        gemm_k<1, 1><<<TOT / BM, NT>>>(Q, nullptr, nullptr, L[l][4], P, TOT,
                                       ei, et, x_in, relbuf, nrm);
        // per-dst segment sums of P
        aggregate_k<<<AGG_BLOCKS, 256>>>(P, oin, cein, oout, ceout, Min, Mout);
        // combined K=600 GEMM: agg = Min@w_in + Mout@w_out + x@(diag(lr)w_loop)
        gemm_k<0, 3><<<(NE + BM - 1) / BM, NT>>>(Min, Mout, x_in, Bcat, agg, NE,
                                                 nullptr, nullptr, nullptr, nullptr,
                                                 nullptr);
        // BN + tanh
        bn_stats_k<<<BN_BLOCKS, 128>>>(agg, sum, sumsq);
        bn_final_k<<<1, 224>>>(sum, sumsq, L[l][7], L[l][8], cA, cB);
        bn_apply_k<<<(NE * D / 2 + 255) / 256, 256>>>(agg, cA, cB, x_out);
        // rel update
        gemm_k<0, 1><<<(R2 + BM - 1) / BM, NT>>>(r_in, nullptr, nullptr, L[l][3],
                                                 r_out, R2, nullptr, nullptr,
                                                 nullptr, nullptr, nullptr);
    }

    gather_k<<<NB, 128>>>(out_x, sub, out_sub);
    gather_k<<<NB, 128>>>(r2, rel, out_rel);
}

// round 7
// speedup vs baseline: 1.4166x; 1.1082x over previous
#include <cuda_runtime.h>
#include <math.h>
#include <stdint.h>

#define D      200
#define NE     40000
#define TOT    160000
#define EHALF  80000
#define R2     200
#define NB     1024
#define EPSV   1e-5f

// ---------------- scratch (static device globals; no allocation) ----------------
__device__ float g_deg[2 * NE];
__device__ float g_norm[TOT];
__device__ int   g_cnt_in[NE], g_cnt_out[NE];
__device__ int   g_off_in[NE + 1], g_off_out[NE + 1];
__device__ int   g_cur_in[NE], g_cur_out[NE];
__device__ int   g_ce_in[EHALF], g_ce_out[EHALF];
__device__ float g_relbuf[(R2 + 1) * D];
__device__ float g_r1[R2 * D];
__device__ float g_r2[R2 * D];
__device__ float g_Bcat[3 * D * D];
__device__ float g_Q[(size_t)TOT * D];
__device__ float g_P[(size_t)TOT * D];
__device__ float g_Min[NE * D];
__device__ float g_Mout[NE * D];
__device__ float g_agg[NE * D];
__device__ float g_x1[NE * D];
__device__ float g_sum[D], g_sumsq[D], g_cA[D], g_cB[D];

// packed f32x2 FMA (sm_103a FFMA2 — PTX only)
__device__ __forceinline__ void fma2(float2& c, float2 a, float2 b) {
    unsigned long long cc = *reinterpret_cast<const unsigned long long*>(&c);
    unsigned long long aa = *reinterpret_cast<const unsigned long long*>(&a);
    unsigned long long bb = *reinterpret_cast<const unsigned long long*>(&b);
    asm("fma.rn.f32x2 %0, %1, %2, %0;" : "+l"(cc) : "l"(aa), "l"(bb));
    c = *reinterpret_cast<float2*>(&cc);
}

// ---------------- degree + per-side dst counts ----------------
__global__ void degcnt_k(const int* __restrict__ ei, float* __restrict__ deg,
                         int* __restrict__ cin, int* __restrict__ cout) {
    int i = blockIdx.x * blockDim.x + threadIdx.x;
    if (i < TOT) {
        int off = (i >= EHALF) ? NE : 0;
        atomicAdd(&deg[off + ei[i]], 1.0f);
        int dst = ei[TOT + i];
        if (i < EHALF) atomicAdd(&cin[dst], 1);
        else           atomicAdd(&cout[dst], 1);
    }
}

__global__ void norm_k(const int* __restrict__ ei, const float* __restrict__ deg,
                       float* __restrict__ nrm) {
    int i = blockIdx.x * blockDim.x + threadIdx.x;
    if (i < TOT) {
        int off = (i >= EHALF) ? NE : 0;
        float a = deg[off + ei[i]];
        float b = deg[off + ei[TOT + i]];
        float va = (a > 0.f) ? rsqrtf(a) : 0.f;
        float vb = (b > 0.f) ? rsqrtf(b) : 0.f;
        nrm[i] = va * vb;
    }
}

// ---------------- CSR scan (both sides in one launch) + fill ----------------
#define SCAN_T 1024
__global__ void scan2_k(const int* __restrict__ cnt_in, int* __restrict__ off_in,
                        int* __restrict__ cur_in,
                        const int* __restrict__ cnt_out, int* __restrict__ off_out,
                        int* __restrict__ cur_out) {
    const int* cnt = blockIdx.x ? cnt_out : cnt_in;
    int* off       = blockIdx.x ? off_out : off_in;
    int* cur       = blockIdx.x ? cur_out : cur_in;
    __shared__ int part[SCAN_T];
    int t = threadIdx.x;
    const int CH = (NE + SCAN_T - 1) / SCAN_T;
    int base = t * CH;
    int s = 0;
    for (int i = 0; i < CH; i++) {
        int idx = base + i;
        if (idx < NE) s += cnt[idx];
    }
    part[t] = s;
    __syncthreads();
    for (int d = 1; d < SCAN_T; d <<= 1) {
        int v = (t >= d) ? part[t - d] : 0;
        __syncthreads();
        part[t] += v;
        __syncthreads();
    }
    int run = (t > 0) ? part[t - 1] : 0;
    for (int i = 0; i < CH; i++) {
        int idx = base + i;
        if (idx < NE) {
            off[idx] = run;
            cur[idx] = run;
            run += cnt[idx];
        }
    }
    if (t == SCAN_T - 1) off[NE] = EHALF;
}

__global__ void fill_k(const int* __restrict__ ei, int* __restrict__ cur_in,
                       int* __restrict__ cur_out, int* __restrict__ ce_in,
                       int* __restrict__ ce_out) {
    int e = blockIdx.x * blockDim.x + threadIdx.x;
    if (e < TOT) {
        int dst = ei[TOT + e];
        if (e < EHALF) { int p = atomicAdd(&cur_in[dst], 1);  ce_in[p] = e; }
        else           { int p = atomicAdd(&cur_out[dst], 1); ce_out[p] = e; }
    }
}

// ---------------- Bcat = [w_in ; w_out ; diag(loop_rel)@w_loop] ----------------
__global__ void prep_bcat_k(const float* __restrict__ w_in, const float* __restrict__ w_out,
                            const float* __restrict__ w_loop, const float* __restrict__ lr,
                            float* __restrict__ Bc) {
    int i = blockIdx.x * blockDim.x + threadIdx.x;
    if (i >= 3 * D * D) return;
    int r = i / D, c = i - r * D;
    float v;
    if (r < D)            v = w_in[r * D + c];
    else if (r < 2 * D)   v = w_out[(r - D) * D + c];
    else                  v = lr[r - 2 * D] * w_loop[(r - 2 * D) * D + c];
    Bc[i] = v;
}

// ---------------- qualifier feature build (float2) ----------------
__global__ void build_q_k(const float* __restrict__ x, const float* __restrict__ rel,
                          const int* __restrict__ qe, const int* __restrict__ qr,
                          float* __restrict__ Q) {
    int e = blockIdx.x;
    int f = threadIdx.x;
    if (f >= D / 2) return;
    int e0 = qe[e], e1 = qe[TOT + e];
    int r0 = qr[e], r1 = qr[TOT + e];
    float2 a = ((const float2*)(x + (size_t)e0 * D))[f];
    float2 b = ((const float2*)(rel + (size_t)r0 * D))[f];
    float2 c = ((const float2*)(x + (size_t)e1 * D))[f];
    float2 d = ((const float2*)(rel + (size_t)r1 * D))[f];
    float2 o;
    o.x = a.x * b.x + c.x * d.x;
    o.y = a.y * b.y + c.y * d.y;
    ((float2*)(Q + (size_t)e * D))[f] = o;
}

// ---------------- cp.async pipelined FFMA2 GEMM (param BM/NT, segmented A) ----------------
// MODE 0: C[gm] = acc (plain store)
// MODE 1: C[gm] = nrm[gm] * x[ei[gm]] * (0.5*rel[et[gm]] + 0.5*acc)
constexpr int BK = 10, NSTG = 3;

template <int MODE, int NSEG, int BMT, int NTT, int OCC>
__global__ __launch_bounds__(NTT, OCC)
void gemm_k(const float* A0, const float* A1, const float* A2,
            const float* __restrict__ Bw, float* C, int M,
            const int* __restrict__ ei, const int* __restrict__ et,
            const float* __restrict__ x, const float* __restrict__ rel,
            const float* __restrict__ nrm) {
    static_assert(BMT == NTT / 2, "geometry");
    __shared__ __align__(16) float As[NSTG][BMT * BK];
    __shared__ __align__(16) float Bs[NSTG][BK * D];

    const int t  = threadIdx.x;
    const int tx = t & 3;        // float2-col group 0..3
    const int ty = t >> 2;       // row pair
    const int m0 = blockIdx.x * BMT;
    constexpr int NIT = NSEG * (D / BK);

    uint32_t sA = (uint32_t)__cvta_generic_to_shared(&As[0][0]);
    uint32_t sB = (uint32_t)__cvta_generic_to_shared(&Bs[0][0]);

    auto issue_tile = [&](int tile) {
        int s = tile % NSTG;
        int seg = (NSEG == 1) ? 0 : tile / (D / BK);
        int k0 = tile * BK - seg * D;              // col within segment
        const float* Ause = (NSEG == 1) ? A0
                           : (seg == 0 ? A0 : (seg == 1 ? A1 : A2));
        for (int i = t; i < BMT * BK / 2; i += NTT) {   // 8B chunks
            int r = i / 5, cc = i - r * 5;
            int gm = m0 + r;
            const float* src = Ause + (size_t)gm * D + k0 + cc * 2;
            int sz = (gm < M) ? 8 : 0;
            asm volatile("cp.async.ca.shared.global [%0], [%1], 8, %2;\n"
                         :: "r"(sA + (uint32_t)((s * BMT * BK + r * BK + cc * 2) * 4)),
                            "l"(src), "r"(sz));
        }
        int kb = tile * BK;                             // row in B (global K)
        for (int i = t; i < BK * D / 4; i += NTT) {     // 500 16B chunks
            int rr = i / 50, cc = i - rr * 50;
            const float* src = Bw + (size_t)(kb + rr) * D + cc * 4;
            asm volatile("cp.async.ca.shared.global [%0], [%1], 16;\n"
                         :: "r"(sB + (uint32_t)((s * BK * D + rr * D + cc * 4) * 4)),
                            "l"(src));
        }
        asm volatile("cp.async.commit_group;\n");
    };

    issue_tile(0);
    issue_tile(1);

    float2 acc0[25], acc1[25];
#pragma unroll
    for (int j = 0; j < 25; j++) {
        acc0[j] = make_float2(0.f, 0.f);
        acc1[j] = make_float2(0.f, 0.f);
    }

    const int r0 = 2 * ty * BK, r1 = (2 * ty + 1) * BK;
    for (int it = 0; it < NIT; it++) {
        asm volatile("cp.async.wait_group 1;\n");
        __syncthreads();
        const float* as = &As[it % NSTG][0];
        const float* bs = &Bs[it % NSTG][0];
#pragma unroll
        for (int kk = 0; kk < BK; kk += 2) {
            float2 a0 = *(const float2*)(as + r0 + kk);
            float2 a1 = *(const float2*)(as + r1 + kk);
            float2 a00 = make_float2(a0.x, a0.x), a01 = make_float2(a0.y, a0.y);
            float2 a10 = make_float2(a1.x, a1.x), a11 = make_float2(a1.y, a1.y);
            const float2* b0 = (const float2*)(bs + kk * D);
            const float2* b1 = (const float2*)(bs + (kk + 1) * D);
#pragma unroll
            for (int j = 0; j < 25; j++) {
                float2 bv0 = b0[tx + 4 * j];
                float2 bv1 = b1[tx + 4 * j];
                fma2(acc0[j], a00, bv0);
                fma2(acc1[j], a10, bv0);
                fma2(acc0[j], a01, bv1);
                fma2(acc1[j], a11, bv1);
            }
        }
        __syncthreads();
        if (it + 2 < NIT) issue_tile(it + 2);
        else asm volatile("cp.async.commit_group;\n");
    }

#pragma unroll
    for (int rr = 0; rr < 2; rr++) {
        int gm = m0 + 2 * ty + rr;
        if (gm >= M) continue;
        float2* accp = rr ? acc1 : acc0;
        float2* cp = (float2*)(C + (size_t)gm * D);
        if (MODE == 0) {
#pragma unroll
            for (int j = 0; j < 25; j++) cp[tx + 4 * j] = accp[j];
        } else {
            int sI = ei[gm];
            int ev = et[gm];
            float nm = nrm[gm];
            const float2* xr = (const float2*)(x + (size_t)sI * D);
            const float2* rv = (const float2*)(rel + (size_t)ev * D);
#pragma unroll
            for (int j = 0; j < 25; j++) {
                int c2 = tx + 4 * j;
                float2 q = accp[j], rl = rv[c2], xx = xr[c2];
                float2 o;
                o.x = nm * xx.x * (0.5f * rl.x + 0.5f * q.x);
                o.y = nm * xx.y * (0.5f * rl.y + 0.5f * q.y);
                cp[c2] = o;
            }
        }
    }
}

// ---------------- per-dst CSR segment-sum of P (norm pre-applied) ----------------
constexpr int AGG_BLOCKS = NE / 2;   // 20000
__global__ __launch_bounds__(256)
void aggregate_k(const float* __restrict__ Pm,
                 const int* __restrict__ off_in, const int* __restrict__ ce_in,
                 const int* __restrict__ off_out, const int* __restrict__ ce_out,
                 float* __restrict__ Min, float* __restrict__ Mout) {
    int f2 = threadIdx.x & 127;
    if (f2 >= D / 2) return;
    int r = blockIdx.x * 2 + (threadIdx.x >> 7);

    float2 vi = make_float2(0.f, 0.f);
    int j0 = off_in[r], j1 = off_in[r + 1];
    for (int j = j0; j < j1; j++) {
        float2 m = ((const float2*)(Pm + (size_t)ce_in[j] * D))[f2];
        vi.x += m.x;
        vi.y += m.y;
    }
    ((float2*)(Min + (size_t)r * D))[f2] = vi;

    float2 vo = make_float2(0.f, 0.f);
    j0 = off_out[r]; j1 = off_out[r + 1];
    for (int j = j0; j < j1; j++) {
        float2 m = ((const float2*)(Pm + (size_t)ce_out[j] * D))[f2];
        vo.x += m.x;
        vo.y += m.y;
    }
    ((float2*)(Mout + (size_t)r * D))[f2] = vo;
}

// ---------------- BN stats / finalize / apply ----------------
constexpr int BN_BLOCKS = 1600, BN_ROWS = NE / BN_BLOCKS;  // 25 rows/block
__global__ __launch_bounds__(128)
void bn_stats_k(const float* __restrict__ t, float* __restrict__ sum,
                float* __restrict__ sumsq) {
    int f2 = threadIdx.x;
    if (f2 >= D / 2) return;
    int r0 = blockIdx.x * BN_ROWS;
    float sx = 0.f, sy = 0.f, qx = 0.f, qy = 0.f;
    for (int r = r0; r < r0 + BN_ROWS; r++) {
        float2 v = ((const float2*)(t + (size_t)r * D))[f2];
        sx += v.x; sy += v.y;
        qx += v.x * v.x; qy += v.y * v.y;
    }
    atomicAdd(&sum[2 * f2], sx);
    atomicAdd(&sum[2 * f2 + 1], sy);
    atomicAdd(&sumsq[2 * f2], qx);
    atomicAdd(&sumsq[2 * f2 + 1], qy);
}

__global__ void bn_final_k(const float* __restrict__ sum, const float* __restrict__ sumsq,
                           const float* __restrict__ gamma, const float* __restrict__ beta,
                           float* __restrict__ cA, float* __restrict__ cB) {
    int f = threadIdx.x;
    if (f >= D) return;
    float mean = sum[f] * (1.f / NE);
    float var  = sumsq[f] * (1.f / NE) - mean * mean;
    if (var < 0.f) var = 0.f;
    float rs = rsqrtf(var * (1.f / 9.f) + EPSV);
    float a  = gamma[f] * rs * (1.f / 3.f);
    cA[f] = a;
    cB[f] = beta[f] - a * mean;
}

__global__ void bn_apply_k(const float* __restrict__ t, const float* __restrict__ cA,
                           const float* __restrict__ cB, float* __restrict__ xo) {
    int i = blockIdx.x * blockDim.x + threadIdx.x;
    if (i < NE * D / 2) {
        int f2 = i % (D / 2);
        float2 v = ((const float2*)t)[i];
        float2 o;
        o.x = tanhf(cA[2 * f2] * v.x + cB[2 * f2]);
        o.y = tanhf(cA[2 * f2 + 1] * v.y + cB[2 * f2 + 1]);
        ((float2*)xo)[i] = o;
    }
}

// ---------------- output gathers ----------------
__global__ void gather_k(const float* __restrict__ src, const int* __restrict__ idx,
                         float* __restrict__ out) {
    int b = blockIdx.x;
    int f = threadIdx.x;
    if (f < D / 2) {
        ((float2*)(out + (size_t)b * D))[f] =
            ((const float2*)(src + (size_t)idx[b] * D))[f];
    }
}

// ---------------- driver ----------------
extern "C" void kernel_launch(void* const* d_in, const int* in_sizes, int n_in,
                              void* d_out, int out_size) {
    const int* ei  = (const int*)d_in[0];
    const int* et  = (const int*)d_in[1];
    const int* qe  = (const int*)d_in[2];
    const int* qr  = (const int*)d_in[3];
    const int* sub = (const int*)d_in[4];
    const int* rel = (const int*)d_in[5];
    const float* init_embed = (const float*)d_in[6];
    const float* init_rel   = (const float*)d_in[7];
    const float* L[2][9];
    for (int l = 0; l < 2; l++)
        for (int p = 0; p < 9; p++) L[l][p] = (const float*)d_in[8 + l * 9 + p];

    float *deg, *nrm, *relbuf, *r1, *r2, *Bcat, *Q, *P, *Min, *Mout, *agg, *x1;
    float *sum, *sumsq, *cA, *cB;
    int *cin, *cout, *oin, *oout, *curin, *curout, *cein, *ceout;
    cudaGetSymbolAddress((void**)&deg,    g_deg);
    cudaGetSymbolAddress((void**)&nrm,    g_norm);
    cudaGetSymbolAddress((void**)&cin,    g_cnt_in);
    cudaGetSymbolAddress((void**)&cout,   g_cnt_out);
    cudaGetSymbolAddress((void**)&oin,    g_off_in);
    cudaGetSymbolAddress((void**)&oout,   g_off_out);
    cudaGetSymbolAddress((void**)&curin,  g_cur_in);
    cudaGetSymbolAddress((void**)&curout, g_cur_out);
    cudaGetSymbolAddress((void**)&cein,   g_ce_in);
    cudaGetSymbolAddress((void**)&ceout,  g_ce_out);
    cudaGetSymbolAddress((void**)&relbuf, g_relbuf);
    cudaGetSymbolAddress((void**)&r1,     g_r1);
    cudaGetSymbolAddress((void**)&r2,     g_r2);
    cudaGetSymbolAddress((void**)&Bcat,   g_Bcat);
    cudaGetSymbolAddress((void**)&Q,      g_Q);
    cudaGetSymbolAddress((void**)&P,      g_P);
    cudaGetSymbolAddress((void**)&Min,    g_Min);
    cudaGetSymbolAddress((void**)&Mout,   g_Mout);
    cudaGetSymbolAddress((void**)&agg,    g_agg);
    cudaGetSymbolAddress((void**)&x1,     g_x1);
    cudaGetSymbolAddress((void**)&sum,    g_sum);
    cudaGetSymbolAddress((void**)&sumsq,  g_sumsq);
    cudaGetSymbolAddress((void**)&cA,     g_cA);
    cudaGetSymbolAddress((void**)&cB,     g_cB);

    float* out     = (float*)d_out;
    float* out_sub = out;
    float* out_rel = out + NB * D;
    float* out_x   = out + 2 * NB * D;

    // graph structure (layer-invariant)
    cudaMemsetAsync(deg, 0, 2 * NE * sizeof(float));
    cudaMemsetAsync(cin, 0, NE * sizeof(int));
    cudaMemsetAsync(cout, 0, NE * sizeof(int));
    degcnt_k<<<(TOT + 255) / 256, 256>>>(ei, deg, cin, cout);
    norm_k<<<(TOT + 255) / 256, 256>>>(ei, deg, nrm);
    scan2_k<<<2, SCAN_T>>>(cin, oin, curin, cout, oout, curout);
    fill_k<<<(TOT + 255) / 256, 256>>>(ei, curin, curout, cein, ceout);

    for (int l = 0; l < 2; l++) {
        const float* x_in = l ? x1 : init_embed;
        const float* r_in = l ? r1 : init_rel;
        float* x_out = l ? out_x : x1;
        float* r_out = l ? r2 : r1;

        cudaMemcpyAsync(relbuf, r_in, R2 * D * sizeof(float), cudaMemcpyDeviceToDevice);
        cudaMemcpyAsync(relbuf + R2 * D, L[l][5], D * sizeof(float), cudaMemcpyDeviceToDevice);
        cudaMemsetAsync(sum, 0, D * sizeof(float));
        cudaMemsetAsync(sumsq, 0, D * sizeof(float));

        prep_bcat_k<<<(3 * D * D + 255) / 256, 256>>>(L[l][1], L[l][2], L[l][0], L[l][5], Bcat);
        build_q_k<<<TOT, 128>>>(x_in, relbuf, qe, qr, Q);
        // qual GEMM + fused P construction (norm folded in); big grid -> BM=128 fine
        gemm_k<1, 1, 128, 256, 2><<<TOT / 128, 256>>>(Q, nullptr, nullptr, L[l][4],
                                                      P, TOT, ei, et, x_in, relbuf, nrm);
        // per-dst segment sums of P
        aggregate_k<<<AGG_BLOCKS, 256>>>(P, oin, cein, oout, ceout, Min, Mout);
        // combined K=600 GEMM (BM=64, 4 blocks/SM to kill wave-quantization tail)
        gemm_k<0, 3, 64, 128, 4><<<(NE + 63) / 64, 128>>>(Min, Mout, x_in, Bcat,
                                                          agg, NE, nullptr, nullptr,
                                                          nullptr, nullptr, nullptr);
        // BN + tanh
        bn_stats_k<<<BN_BLOCKS, 128>>>(agg, sum, sumsq);
        bn_final_k<<<1, 224>>>(sum, sumsq, L[l][7], L[l][8], cA, cB);
        bn_apply_k<<<(NE * D / 2 + 255) / 256, 256>>>(agg, cA, cB, x_out);
        // rel update (tiny)
        gemm_k<0, 1, 128, 256, 2><<<(R2 + 127) / 128, 256>>>(r_in, nullptr, nullptr,
                                                             L[l][3], r_out, R2,
                                                             nullptr, nullptr, nullptr,
                                                             nullptr, nullptr);
    }

    gather_k<<<NB, 128>>>(out_x, sub, out_sub);
    gather_k<<<NB, 128>>>(r2, rel, out_rel);
}

// round 14
// speedup vs baseline: 1.4815x; 1.0458x over previous
#include <cuda_runtime.h>
#include <cuda_bf16.h>
#include <mma.h>
#include <math.h>
#include <stdint.h>

using namespace nvcuda;

#define D      200
#define KP     208          // K and N padded to 13*16 for wmma
#define NE     40000
#define TOT    160000
#define EHALF  80000
#define R2     200
#define NB     1024
#define EPSV   1e-5f

// ================= scratch (static device globals; no allocation) =================
__device__ float g_deg[2 * NE];
__device__ float g_norm[TOT];
__device__ int   g_cnt_in[NE], g_cnt_out[NE];
__device__ int   g_off_in[NE + 1], g_off_out[NE + 1];
__device__ int   g_cur_in[NE], g_cur_out[NE];
__device__ int   g_ce_in[EHALF], g_ce_out[EHALF];
__device__ float g_relbuf[(R2 + 1) * D];
__device__ float g_r1[R2 * D];
__device__ float g_r2[R2 * D];
__device__ float g_Bcat[3 * D * D];
__device__ __align__(256) __nv_bfloat16 g_Qhi[(size_t)TOT * KP];
__device__ __align__(256) __nv_bfloat16 g_Qlo[(size_t)TOT * KP];
__device__ __align__(256) __nv_bfloat16 g_Whi[KP * KP];
__device__ __align__(256) __nv_bfloat16 g_Wlo[KP * KP];
__device__ float g_P[(size_t)TOT * D];
__device__ float g_Min[NE * D];
__device__ float g_Mout[NE * D];
__device__ float g_agg[NE * D];
__device__ float g_x1[NE * D];
__device__ float g_sum[D], g_sumsq[D], g_cA[D], g_cB[D];

// packed f32x2 FMA (sm_103a FFMA2 — PTX only)
__device__ __forceinline__ void fma2(float2& c, float2 a, float2 b) {
    unsigned long long cc = *reinterpret_cast<const unsigned long long*>(&c);
    unsigned long long aa = *reinterpret_cast<const unsigned long long*>(&a);
    unsigned long long bb = *reinterpret_cast<const unsigned long long*>(&b);
    asm("fma.rn.f32x2 %0, %1, %2, %0;" : "+l"(cc) : "l"(aa), "l"(bb));
    c = *reinterpret_cast<float2*>(&cc);
}

// ================= graph preprocessing =================
__global__ void degcnt_k(const int* __restrict__ ei, float* __restrict__ deg,
                         int* __restrict__ cin, int* __restrict__ cout) {
    int i = blockIdx.x * blockDim.x + threadIdx.x;
    if (i < TOT) {
        int off = (i >= EHALF) ? NE : 0;
        atomicAdd(&deg[off + ei[i]], 1.0f);
        int dst = ei[TOT + i];
        if (i < EHALF) atomicAdd(&cin[dst], 1);
        else           atomicAdd(&cout[dst], 1);
    }
}

__global__ void norm_k(const int* __restrict__ ei, const float* __restrict__ deg,
                       float* __restrict__ nrm) {
    int i = blockIdx.x * blockDim.x + threadIdx.x;
    if (i < TOT) {
        int off = (i >= EHALF) ? NE : 0;
        float a = deg[off + ei[i]];
        float b = deg[off + ei[TOT + i]];
        float va = (a > 0.f) ? rsqrtf(a) : 0.f;
        float vb = (b > 0.f) ? rsqrtf(b) : 0.f;
        nrm[i] = va * vb;
    }
}

#define SCAN_T 1024
__global__ void scan2_k(const int* __restrict__ cnt_in, int* __restrict__ off_in,
                        int* __restrict__ cur_in,
                        const int* __restrict__ cnt_out, int* __restrict__ off_out,
                        int* __restrict__ cur_out) {
    const int* cnt = blockIdx.x ? cnt_out : cnt_in;
    int* off       = blockIdx.x ? off_out : off_in;
    int* cur       = blockIdx.x ? cur_out : cur_in;
    __shared__ int part[SCAN_T];
    int t = threadIdx.x;
    const int CH = (NE + SCAN_T - 1) / SCAN_T;
    int base = t * CH;
    int s = 0;
    for (int i = 0; i < CH; i++) {
        int idx = base + i;
        if (idx < NE) s += cnt[idx];
    }
    part[t] = s;
    __syncthreads();
    for (int d = 1; d < SCAN_T; d <<= 1) {
        int v = (t >= d) ? part[t - d] : 0;
        __syncthreads();
        part[t] += v;
        __syncthreads();
    }
    int run = (t > 0) ? part[t - 1] : 0;
    for (int i = 0; i < CH; i++) {
        int idx = base + i;
        if (idx < NE) {
            off[idx] = run;
            cur[idx] = run;
            run += cnt[idx];
        }
    }
    if (t == SCAN_T - 1) off[NE] = EHALF;
}

__global__ void fill_k(const int* __restrict__ ei, int* __restrict__ cur_in,
                       int* __restrict__ cur_out, int* __restrict__ ce_in,
                       int* __restrict__ ce_out) {
    int e = blockIdx.x * blockDim.x + threadIdx.x;
    if (e < TOT) {
        int dst = ei[TOT + e];
        if (e < EHALF) { int p = atomicAdd(&cur_in[dst], 1);  ce_in[p] = e; }
        else           { int p = atomicAdd(&cur_out[dst], 1); ce_out[p] = e; }
    }
}

// ================= weight prep =================
__global__ void prep_bcat_k(const float* __restrict__ w_in, const float* __restrict__ w_out,
                            const float* __restrict__ w_loop, const float* __restrict__ lr,
                            float* __restrict__ Bc) {
    int i = blockIdx.x * blockDim.x + threadIdx.x;
    if (i >= 3 * D * D) return;
    int r = i / D, c = i - r * D;
    float v;
    if (r < D)            v = w_in[r * D + c];
    else if (r < 2 * D)   v = w_out[(r - D) * D + c];
    else                  v = lr[r - 2 * D] * w_loop[(r - 2 * D) * D + c];
    Bc[i] = v;
}

// w_q[200,200] -> bf16 hi/lo row-major [KP][KP], zero padded
__global__ void prep_wimg_k(const float* __restrict__ W,
                            __nv_bfloat16* __restrict__ hi, __nv_bfloat16* __restrict__ lo) {
    int i = blockIdx.x * blockDim.x + threadIdx.x;
    if (i >= KP * KP) return;
    int k = i / KP, n = i - k * KP;
    float v = (k < D && n < D) ? W[k * D + n] : 0.f;
    __nv_bfloat16 h = __float2bfloat16(v);
    hi[i] = h;
    lo[i] = __float2bfloat16(v - __bfloat162float(h));
}

// ================= qualifier build -> bf16 split row-major [TOT][KP] =================
__global__ __launch_bounds__(128)
void build_q_k(const float* __restrict__ x, const float* __restrict__ rel,
               const int* __restrict__ qe, const int* __restrict__ qr,
               __nv_bfloat16* __restrict__ qhi, __nv_bfloat16* __restrict__ qlo) {
    int e = blockIdx.x;
    int f2 = threadIdx.x;            // col pair (2f2, 2f2+1); cols up to KP
    if (f2 >= KP / 2) return;
    float2 o = make_float2(0.f, 0.f);
    if (f2 < D / 2) {
        int e0 = qe[e], e1 = qe[TOT + e];
        int r0 = qr[e], r1 = qr[TOT + e];
        float2 a = ((const float2*)(x + (size_t)e0 * D))[f2];
        float2 b = ((const float2*)(rel + (size_t)r0 * D))[f2];
        float2 c = ((const float2*)(x + (size_t)e1 * D))[f2];
        float2 d = ((const float2*)(rel + (size_t)r1 * D))[f2];
        o.x = a.x * b.x + c.x * d.x;
        o.y = a.y * b.y + c.y * d.y;
    }
    __nv_bfloat16 hx = __float2bfloat16(o.x), hy = __float2bfloat16(o.y);
    __nv_bfloat162 hv; hv.x = hx; hv.y = hy;
    __nv_bfloat162 lv;
    lv.x = __float2bfloat16(o.x - __bfloat162float(hx));
    lv.y = __float2bfloat16(o.y - __bfloat162float(hy));
    size_t off = (size_t)e * KP + 2 * f2;
    *(__nv_bfloat162*)(qhi + off) = hv;
    *(__nv_bfloat162*)(qlo + off) = lv;
}

// ================= wmma (HMMA) qual GEMM (bf16 split) + fused P epilogue =================
// Block = 64 rows, 4 warps x 16 rows. 13 n-tiles x 13 k-tiles of 16x16x16.
// acc = Qhi@Whi + Qhi@Wlo + Qlo@Whi (fp32); P[gm] = nrm*x[src]*(0.5*rel[et]+0.5*acc)
constexpr int WMMA_LDC  = 212;                       // smem row stride (floats)
constexpr int WMMA_SMEM = 4 * 16 * WMMA_LDC * 4;     // 54272 bytes

__global__ __launch_bounds__(128, 2)
void wmma_gemm1_k(const __nv_bfloat16* __restrict__ qhi, const __nv_bfloat16* __restrict__ qlo,
                  const __nv_bfloat16* __restrict__ whi, const __nv_bfloat16* __restrict__ wlo,
                  float* __restrict__ P,
                  const int* __restrict__ ei, const int* __restrict__ et,
                  const float* __restrict__ x, const float* __restrict__ rel,
                  const float* __restrict__ nrm) {
    extern __shared__ float csm[];
    const int wid = threadIdx.x >> 5, lid = threadIdx.x & 31;
    const int row0 = blockIdx.x * 64 + wid * 16;

    wmma::fragment<wmma::accumulator, 16, 16, 16, float> c[13];
#pragma unroll
    for (int j = 0; j < 13; j++) wmma::fill_fragment(c[j], 0.f);

    for (int k = 0; k < 13; k++) {
        wmma::fragment<wmma::matrix_a, 16, 16, 16, __nv_bfloat16, wmma::row_major> ah, al;
        wmma::load_matrix_sync(ah, qhi + (size_t)row0 * KP + k * 16, KP);
        wmma::load_matrix_sync(al, qlo + (size_t)row0 * KP + k * 16, KP);
#pragma unroll
        for (int j = 0; j < 13; j++) {
            wmma::fragment<wmma::matrix_b, 16, 16, 16, __nv_bfloat16, wmma::row_major> bh, bl;
            wmma::load_matrix_sync(bh, whi + k * 16 * KP + j * 16, KP);
            wmma::load_matrix_sync(bl, wlo + k * 16 * KP + j * 16, KP);
            wmma::mma_sync(c[j], ah, bh, c[j]);
            wmma::mma_sync(c[j], ah, bl, c[j]);
            wmma::mma_sync(c[j], al, bh, c[j]);
        }
    }

    float* buf = csm + wid * 16 * WMMA_LDC;
#pragma unroll
    for (int j = 0; j < 13; j++)
        wmma::store_matrix_sync(buf + j * 16, c[j], WMMA_LDC, wmma::mem_row_major);
    __syncwarp();

    // fused epilogue: this warp's 16 rows
    for (int rr = 0; rr < 16; rr++) {
        int gm = row0 + rr;
        int sI = ei[gm], ev = et[gm];
        float nm = nrm[gm];
        const float4* xr = (const float4*)(x + (size_t)sI * D);
        const float4* rv = (const float4*)(rel + (size_t)ev * D);
        const float4* cb = (const float4*)(buf + rr * WMMA_LDC);
        float4* pp = (float4*)(P + (size_t)gm * D);
        for (int q = lid; q < D / 4; q += 32) {
            float4 acc = cb[q], xx = xr[q], rl = rv[q], o;
            o.x = nm * xx.x * (0.5f * rl.x + 0.5f * acc.x);
            o.y = nm * xx.y * (0.5f * rl.y + 0.5f * acc.y);
            o.z = nm * xx.z * (0.5f * rl.z + 0.5f * acc.z);
            o.w = nm * xx.w * (0.5f * rl.w + 0.5f * acc.w);
            pp[q] = o;
        }
    }
}

// ================= FFMA2 SIMT GEMM (K600 + rel update) — unchanged from R7 =================
constexpr int BK = 10, NSTG = 3;

template <int NSEG, int BMT, int NTT, int OCC>
__global__ __launch_bounds__(NTT, OCC)
void gemm_k(const float* A0, const float* A1, const float* A2,
            const float* __restrict__ Bw, float* C, int M) {
    static_assert(BMT == NTT / 2, "geometry");
    __shared__ __align__(16) float As[NSTG][BMT * BK];
    __shared__ __align__(16) float Bs[NSTG][BK * D];

    const int t  = threadIdx.x;
    const int tx = t & 3;
    const int ty = t >> 2;
    const int m0 = blockIdx.x * BMT;
    constexpr int NIT = NSEG * (D / BK);

    uint32_t sA = (uint32_t)__cvta_generic_to_shared(&As[0][0]);
    uint32_t sB = (uint32_t)__cvta_generic_to_shared(&Bs[0][0]);

    auto issue_tile = [&](int tile) {
        int s = tile % NSTG;
        int seg = (NSEG == 1) ? 0 : tile / (D / BK);
        int k0 = tile * BK - seg * D;
        const float* Ause = (NSEG == 1) ? A0
                           : (seg == 0 ? A0 : (seg == 1 ? A1 : A2));
        for (int i = t; i < BMT * BK / 2; i += NTT) {
            int r = i / 5, cc = i - r * 5;
            int gm = m0 + r;
            const float* src = Ause + (size_t)gm * D + k0 + cc * 2;
            int sz = (gm < M) ? 8 : 0;
            asm volatile("cp.async.ca.shared.global [%0], [%1], 8, %2;\n"
                         :: "r"(sA + (uint32_t)((s * BMT * BK + r * BK + cc * 2) * 4)),
                            "l"(src), "r"(sz));
        }
        int kb = tile * BK;
        for (int i = t; i < BK * D / 4; i += NTT) {
            int rr = i / 50, cc = i - rr * 50;
            const float* src = Bw + (size_t)(kb + rr) * D + cc * 4;
            asm volatile("cp.async.ca.shared.global [%0], [%1], 16;\n"
                         :: "r"(sB + (uint32_t)((s * BK * D + rr * D + cc * 4) * 4)),
                            "l"(src));
        }
        asm volatile("cp.async.commit_group;\n");
    };

    issue_tile(0);
    issue_tile(1);

    float2 acc0[25], acc1[25];
#pragma unroll
    for (int j = 0; j < 25; j++) {
        acc0[j] = make_float2(0.f, 0.f);
        acc1[j] = make_float2(0.f, 0.f);
    }

    const int r0 = 2 * ty * BK, r1 = (2 * ty + 1) * BK;
    for (int it = 0; it < NIT; it++) {
        asm volatile("cp.async.wait_group 1;\n");
        __syncthreads();
        const float* as = &As[it % NSTG][0];
        const float* bs = &Bs[it % NSTG][0];
#pragma unroll
        for (int kk = 0; kk < BK; kk += 2) {
            float2 a0 = *(const float2*)(as + r0 + kk);
            float2 a1 = *(const float2*)(as + r1 + kk);
            float2 a00 = make_float2(a0.x, a0.x), a01 = make_float2(a0.y, a0.y);
            float2 a10 = make_float2(a1.x, a1.x), a11 = make_float2(a1.y, a1.y);
            const float2* b0 = (const float2*)(bs + kk * D);
            const float2* b1 = (const float2*)(bs + (kk + 1) * D);
#pragma unroll
            for (int j = 0; j < 25; j++) {
                float2 bv0 = b0[tx + 4 * j];
                float2 bv1 = b1[tx + 4 * j];
                fma2(acc0[j], a00, bv0);
                fma2(acc1[j], a10, bv0);
                fma2(acc0[j], a01, bv1);
                fma2(acc1[j], a11, bv1);
            }
        }
        __syncthreads();
        if (it + 2 < NIT) issue_tile(it + 2);
        else asm volatile("cp.async.commit_group;\n");
    }

#pragma unroll
    for (int rr = 0; rr < 2; rr++) {
        int gm = m0 + 2 * ty + rr;
        if (gm >= M) continue;
        float2* accp = rr ? acc1 : acc0;
        float2* cp = (float2*)(C + (size_t)gm * D);
#pragma unroll
        for (int j = 0; j < 25; j++) cp[tx + 4 * j] = accp[j];
    }
}

// ================= per-dst CSR segment-sum of P =================
constexpr int AGG_BLOCKS = NE / 2;   // 20000
__global__ __launch_bounds__(256)
void aggregate_k(const float* __restrict__ Pm,
                 const int* __restrict__ off_in, const int* __restrict__ ce_in,
                 const int* __restrict__ off_out, const int* __restrict__ ce_out,
                 float* __restrict__ Min, float* __restrict__ Mout) {
    int f2 = threadIdx.x & 127;
    if (f2 >= D / 2) return;
    int r = blockIdx.x * 2 + (threadIdx.x >> 7);

    float2 vi = make_float2(0.f, 0.f);
    int j0 = off_in[r], j1 = off_in[r + 1];
    for (int j = j0; j < j1; j++) {
        float2 m = ((const float2*)(Pm + (size_t)ce_in[j] * D))[f2];
        vi.x += m.x;
        vi.y += m.y;
    }
    ((float2*)(Min + (size_t)r * D))[f2] = vi;

    float2 vo = make_float2(0.f, 0.f);
    j0 = off_out[r]; j1 = off_out[r + 1];
    for (int j = j0; j < j1; j++) {
        float2 m = ((const float2*)(Pm + (size_t)ce_out[j] * D))[f2];
        vo.x += m.x;
        vo.y += m.y;
    }
    ((float2*)(Mout + (size_t)r * D))[f2] = vo;
}

// ================= BN =================
constexpr int BN_BLOCKS = 1600, BN_ROWS = NE / BN_BLOCKS;
__global__ __launch_bounds__(128)
void bn_stats_k(const float* __restrict__ t, float* __restrict__ sum,
                float* __restrict__ sumsq) {
    int f2 = threadIdx.x;
    if (f2 >= D / 2) return;
    int r0 = blockIdx.x * BN_ROWS;
    float sx = 0.f, sy = 0.f, qx = 0.f, qy = 0.f;
    for (int r = r0; r < r0 + BN_ROWS; r++) {
        float2 v = ((const float2*)(t + (size_t)r * D))[f2];
        sx += v.x; sy += v.y;
        qx += v.x * v.x; qy += v.y * v.y;
    }
    atomicAdd(&sum[2 * f2], sx);
    atomicAdd(&sum[2 * f2 + 1], sy);
    atomicAdd(&sumsq[2 * f2], qx);
    atomicAdd(&sumsq[2 * f2 + 1], qy);
}

__global__ void bn_final_k(const float* __restrict__ sum, const float* __restrict__ sumsq,
                           const float* __restrict__ gamma, const float* __restrict__ beta,
                           float* __restrict__ cA, float* __restrict__ cB) {
    int f = threadIdx.x;
    if (f >= D) return;
    float mean = sum[f] * (1.f / NE);
    float var  = sumsq[f] * (1.f / NE) - mean * mean;
    if (var < 0.f) var = 0.f;
    float rs = rsqrtf(var * (1.f / 9.f) + EPSV);
    float a  = gamma[f] * rs * (1.f / 3.f);
    cA[f] = a;
    cB[f] = beta[f] - a * mean;
}

__global__ void bn_apply_k(const float* __restrict__ t, const float* __restrict__ cA,
                           const float* __restrict__ cB, float* __restrict__ xo) {
    int i = blockIdx.x * blockDim.x + threadIdx.x;
    if (i < NE * D / 2) {
        int f2 = i % (D / 2);
        float2 v = ((const float2*)t)[i];
        float2 o;
        o.x = tanhf(cA[2 * f2] * v.x + cB[2 * f2]);
        o.y = tanhf(cA[2 * f2 + 1] * v.y + cB[2 * f2 + 1]);
        ((float2*)xo)[i] = o;
    }
}

// ================= output gathers =================
__global__ void gather_k(const float* __restrict__ src, const int* __restrict__ idx,
                         float* __restrict__ out) {
    int b = blockIdx.x;
    int f = threadIdx.x;
    if (f < D / 2) {
        ((float2*)(out + (size_t)b * D))[f] =
            ((const float2*)(src + (size_t)idx[b] * D))[f];
    }
}

// ================= driver =================
extern "C" void kernel_launch(void* const* d_in, const int* in_sizes, int n_in,
                              void* d_out, int out_size) {
    const int* ei  = (const int*)d_in[0];
    const int* et  = (const int*)d_in[1];
    const int* qe  = (const int*)d_in[2];
    const int* qr  = (const int*)d_in[3];
    const int* sub = (const int*)d_in[4];
    const int* rel = (const int*)d_in[5];
    const float* init_embed = (const float*)d_in[6];
    const float* init_rel   = (const float*)d_in[7];
    const float* L[2][9];
    for (int l = 0; l < 2; l++)
        for (int p = 0; p < 9; p++) L[l][p] = (const float*)d_in[8 + l * 9 + p];

    float *deg, *nrm, *relbuf, *r1, *r2, *Bcat, *P, *Min, *Mout, *agg, *x1;
    float *sum, *sumsq, *cA, *cB;
    __nv_bfloat16 *qhi, *qlo, *whi, *wlo;
    int *cin, *cout, *oin, *oout, *curin, *curout, *cein, *ceout;
    cudaGetSymbolAddress((void**)&deg,    g_deg);
    cudaGetSymbolAddress((void**)&nrm,    g_norm);
    cudaGetSymbolAddress((void**)&cin,    g_cnt_in);
    cudaGetSymbolAddress((void**)&cout,   g_cnt_out);
    cudaGetSymbolAddress((void**)&oin,    g_off_in);
    cudaGetSymbolAddress((void**)&oout,   g_off_out);
    cudaGetSymbolAddress((void**)&curin,  g_cur_in);
    cudaGetSymbolAddress((void**)&curout, g_cur_out);
    cudaGetSymbolAddress((void**)&cein,   g_ce_in);
    cudaGetSymbolAddress((void**)&ceout,  g_ce_out);
    cudaGetSymbolAddress((void**)&relbuf, g_relbuf);
    cudaGetSymbolAddress((void**)&r1,     g_r1);
    cudaGetSymbolAddress((void**)&r2,     g_r2);
    cudaGetSymbolAddress((void**)&Bcat,   g_Bcat);
    cudaGetSymbolAddress((void**)&qhi,    g_Qhi);
    cudaGetSymbolAddress((void**)&qlo,    g_Qlo);
    cudaGetSymbolAddress((void**)&whi,    g_Whi);
    cudaGetSymbolAddress((void**)&wlo,    g_Wlo);
    cudaGetSymbolAddress((void**)&P,      g_P);
    cudaGetSymbolAddress((void**)&Min,    g_Min);
    cudaGetSymbolAddress((void**)&Mout,   g_Mout);
    cudaGetSymbolAddress((void**)&agg,    g_agg);
    cudaGetSymbolAddress((void**)&x1,     g_x1);
    cudaGetSymbolAddress((void**)&sum,    g_sum);
    cudaGetSymbolAddress((void**)&sumsq,  g_sumsq);
    cudaGetSymbolAddress((void**)&cA,     g_cA);
    cudaGetSymbolAddress((void**)&cB,     g_cB);

    static int smem_set = 0;
    if (!smem_set) {
        cudaFuncSetAttribute(wmma_gemm1_k, cudaFuncAttributeMaxDynamicSharedMemorySize,
                             WMMA_SMEM);
        smem_set = 1;
    }

    float* out     = (float*)d_out;
    float* out_sub = out;
    float* out_rel = out + NB * D;
    float* out_x   = out + 2 * NB * D;

    // graph structure (layer-invariant)
    cudaMemsetAsync(deg, 0, 2 * NE * sizeof(float));
    cudaMemsetAsync(cin, 0, NE * sizeof(int));
    cudaMemsetAsync(cout, 0, NE * sizeof(int));
    degcnt_k<<<(TOT + 255) / 256, 256>>>(ei, deg, cin, cout);
    norm_k<<<(TOT + 255) / 256, 256>>>(ei, deg, nrm);
    scan2_k<<<2, SCAN_T>>>(cin, oin, curin, cout, oout, curout);
    fill_k<<<(TOT + 255) / 256, 256>>>(ei, curin, curout, cein, ceout);

    for (int l = 0; l < 2; l++) {
        const float* x_in = l ? x1 : init_embed;
        const float* r_in = l ? r1 : init_rel;
        float* x_out = l ? out_x : x1;
        float* r_out = l ? r2 : r1;

        cudaMemcpyAsync(relbuf, r_in, R2 * D * sizeof(float), cudaMemcpyDeviceToDevice);
        cudaMemcpyAsync(relbuf + R2 * D, L[l][5], D * sizeof(float), cudaMemcpyDeviceToDevice);
        cudaMemsetAsync(sum, 0, D * sizeof(float));
        cudaMemsetAsync(sumsq, 0, D * sizeof(float));

        prep_bcat_k<<<(3 * D * D + 255) / 256, 256>>>(L[l][1], L[l][2], L[l][0], L[l][5], Bcat);
        prep_wimg_k<<<(KP * KP + 255) / 256, 256>>>(L[l][4], whi, wlo);
        build_q_k<<<TOT, 128>>>(x_in, relbuf, qe, qr, qhi, qlo);
        // tensor-core (HMMA/wmma) qual GEMM + fused P epilogue
        wmma_gemm1_k<<<TOT / 64, 128, WMMA_SMEM>>>(qhi, qlo, whi, wlo, P, ei, et,
                                                   x_in, relbuf, nrm);
        // per-dst segment sums of P
        aggregate_k<<<AGG_BLOCKS, 256>>>(P, oin, cein, oout, ceout, Min, Mout);
        // combined K=600 GEMM (FFMA2, BM=64, 4 blocks/SM)
        gemm_k<3, 64, 128, 4><<<(NE + 63) / 64, 128>>>(Min, Mout, x_in, Bcat, agg, NE);
        // BN + tanh
        bn_stats_k<<<BN_BLOCKS, 128>>>(agg, sum, sumsq);
        bn_final_k<<<1, 224>>>(sum, sumsq, L[l][7], L[l][8], cA, cB);
        bn_apply_k<<<(NE * D / 2 + 255) / 256, 256>>>(agg, cA, cB, x_out);
        // rel update (tiny)
        gemm_k<1, 128, 256, 2><<<(R2 + 127) / 128, 256>>>(r_in, nullptr, nullptr,
                                                          L[l][3], r_out, R2);
    }

    gather_k<<<NB, 128>>>(out_x, sub, out_sub);
    gather_k<<<NB, 128>>>(r2, rel, out_rel);
}

// round 15
// speedup vs baseline: 2.0958x; 1.4147x over previous
#include <cuda_runtime.h>
#include <cuda_bf16.h>
#include <mma.h>
#include <math.h>
#include <stdint.h>

using namespace nvcuda;

#define D      200
#define KP     208          // K and N padded to 13*16 for wmma
#define NE     40000
#define TOT    160000
#define EHALF  80000
#define R2     200
#define NB     1024
#define EPSV   1e-5f

// ================= scratch (static device globals; no allocation) =================
__device__ float g_deg[2 * NE];
__device__ float g_norm[TOT];
__device__ int   g_cnt_in[NE], g_cnt_out[NE];
__device__ int   g_off_in[NE + 1], g_off_out[NE + 1];
__device__ int   g_cur_in[NE], g_cur_out[NE];
__device__ int   g_ce_in[EHALF], g_ce_out[EHALF];
__device__ float g_relbuf[(R2 + 1) * D];
__device__ float g_r1[R2 * D];
__device__ float g_r2[R2 * D];
__device__ __align__(256) __nv_bfloat16 g_Qhi[(size_t)TOT * KP];
__device__ __align__(256) __nv_bfloat16 g_Qlo[(size_t)TOT * KP];
__device__ __align__(256) __nv_bfloat16 g_Whi[KP * KP];
__device__ __align__(256) __nv_bfloat16 g_Wlo[KP * KP];
// K600 operands (bf16 split, zero-padded; pads never written => stay zero)
__device__ __align__(256) __nv_bfloat16 g_Mih[(size_t)NE * KP];
__device__ __align__(256) __nv_bfloat16 g_Mil[(size_t)NE * KP];
__device__ __align__(256) __nv_bfloat16 g_Moh[(size_t)NE * KP];
__device__ __align__(256) __nv_bfloat16 g_Mol[(size_t)NE * KP];
__device__ __align__(256) __nv_bfloat16 g_Xhi[(size_t)NE * KP];
__device__ __align__(256) __nv_bfloat16 g_Xlo[(size_t)NE * KP];
__device__ __align__(256) __nv_bfloat16 g_BChi[3 * KP * KP];
__device__ __align__(256) __nv_bfloat16 g_BClo[3 * KP * KP];
__device__ float g_P[(size_t)TOT * D];
__device__ float g_agg[NE * D];
__device__ float g_x1[NE * D];
__device__ float g_sum[D], g_sumsq[D], g_cA[D], g_cB[D];

// packed f32x2 FMA (sm_103a FFMA2 — PTX only)
__device__ __forceinline__ void fma2(float2& c, float2 a, float2 b) {
    unsigned long long cc = *reinterpret_cast<const unsigned long long*>(&c);
    unsigned long long aa = *reinterpret_cast<const unsigned long long*>(&a);
    unsigned long long bb = *reinterpret_cast<const unsigned long long*>(&b);
    asm("fma.rn.f32x2 %0, %1, %2, %0;" : "+l"(cc) : "l"(aa), "l"(bb));
    c = *reinterpret_cast<float2*>(&cc);
}

__device__ __forceinline__ void split_store(__nv_bfloat16* hi, __nv_bfloat16* lo,
                                            size_t off, float2 o) {
    __nv_bfloat16 hx = __float2bfloat16(o.x), hy = __float2bfloat16(o.y);
    __nv_bfloat162 hv; hv.x = hx; hv.y = hy;
    __nv_bfloat162 lv;
    lv.x = __float2bfloat16(o.x - __bfloat162float(hx));
    lv.y = __float2bfloat16(o.y - __bfloat162float(hy));
    *(__nv_bfloat162*)(hi + off) = hv;
    *(__nv_bfloat162*)(lo + off) = lv;
}

// ================= graph preprocessing =================
__global__ void degcnt_k(const int* __restrict__ ei, float* __restrict__ deg,
                         int* __restrict__ cin, int* __restrict__ cout) {
    int i = blockIdx.x * blockDim.x + threadIdx.x;
    if (i < TOT) {
        int off = (i >= EHALF) ? NE : 0;
        atomicAdd(&deg[off + ei[i]], 1.0f);
        int dst = ei[TOT + i];
        if (i < EHALF) atomicAdd(&cin[dst], 1);
        else           atomicAdd(&cout[dst], 1);
    }
}

__global__ void norm_k(const int* __restrict__ ei, const float* __restrict__ deg,
                       float* __restrict__ nrm) {
    int i = blockIdx.x * blockDim.x + threadIdx.x;
    if (i < TOT) {
        int off = (i >= EHALF) ? NE : 0;
        float a = deg[off + ei[i]];
        float b = deg[off + ei[TOT + i]];
        float va = (a > 0.f) ? rsqrtf(a) : 0.f;
        float vb = (b > 0.f) ? rsqrtf(b) : 0.f;
        nrm[i] = va * vb;
    }
}

#define SCAN_T 1024
__global__ void scan2_k(const int* __restrict__ cnt_in, int* __restrict__ off_in,
                        int* __restrict__ cur_in,
                        const int* __restrict__ cnt_out, int* __restrict__ off_out,
                        int* __restrict__ cur_out) {
    const int* cnt = blockIdx.x ? cnt_out : cnt_in;
    int* off       = blockIdx.x ? off_out : off_in;
    int* cur       = blockIdx.x ? cur_out : cur_in;
    __shared__ int part[SCAN_T];
    int t = threadIdx.x;
    const int CH = (NE + SCAN_T - 1) / SCAN_T;
    int base = t * CH;
    int s = 0;
    for (int i = 0; i < CH; i++) {
        int idx = base + i;
        if (idx < NE) s += cnt[idx];
    }
    part[t] = s;
    __syncthreads();
    for (int d = 1; d < SCAN_T; d <<= 1) {
        int v = (t >= d) ? part[t - d] : 0;
        __syncthreads();
        part[t] += v;
        __syncthreads();
    }
    int run = (t > 0) ? part[t - 1] : 0;
    for (int i = 0; i < CH; i++) {
        int idx = base + i;
        if (idx < NE) {
            off[idx] = run;
            cur[idx] = run;
            run += cnt[idx];
        }
    }
    if (t == SCAN_T - 1) off[NE] = EHALF;
}

__global__ void fill_k(const int* __restrict__ ei, int* __restrict__ cur_in,
                       int* __restrict__ cur_out, int* __restrict__ ce_in,
                       int* __restrict__ ce_out) {
    int e = blockIdx.x * blockDim.x + threadIdx.x;
    if (e < TOT) {
        int dst = ei[TOT + e];
        if (e < EHALF) { int p = atomicAdd(&cur_in[dst], 1);  ce_in[p] = e; }
        else           { int p = atomicAdd(&cur_out[dst], 1); ce_out[p] = e; }
    }
}

// ================= weight prep =================
// Bcat = [w_in ; w_out ; diag(lr)w_loop] -> bf16 split [3*KP][KP], zero padded
__global__ void prep_bcat_split_k(const float* __restrict__ w_in,
                                  const float* __restrict__ w_out,
                                  const float* __restrict__ w_loop,
                                  const float* __restrict__ lr,
                                  __nv_bfloat16* __restrict__ bh,
                                  __nv_bfloat16* __restrict__ bl) {
    int i = blockIdx.x * blockDim.x + threadIdx.x;
    if (i >= 3 * KP * KP) return;
    int s = i / (KP * KP);
    int rem = i - s * (KP * KP);
    int k = rem / KP, n = rem - k * KP;
    float v = 0.f;
    if (k < D && n < D) {
        if (s == 0)      v = w_in[k * D + n];
        else if (s == 1) v = w_out[k * D + n];
        else             v = lr[k] * w_loop[k * D + n];
    }
    __nv_bfloat16 h = __float2bfloat16(v);
    bh[i] = h;
    bl[i] = __float2bfloat16(v - __bfloat162float(h));
}

// w_q[200,200] -> bf16 hi/lo row-major [KP][KP], zero padded
__global__ void prep_wimg_k(const float* __restrict__ W,
                            __nv_bfloat16* __restrict__ hi, __nv_bfloat16* __restrict__ lo) {
    int i = blockIdx.x * blockDim.x + threadIdx.x;
    if (i >= KP * KP) return;
    int k = i / KP, n = i - k * KP;
    float v = (k < D && n < D) ? W[k * D + n] : 0.f;
    __nv_bfloat16 h = __float2bfloat16(v);
    hi[i] = h;
    lo[i] = __float2bfloat16(v - __bfloat162float(h));
}

// x fp32 [NE][D] -> bf16 split [NE][KP]
__global__ __launch_bounds__(128)
void conv_x_k(const float* __restrict__ x,
              __nv_bfloat16* __restrict__ xh, __nv_bfloat16* __restrict__ xl) {
    int e = blockIdx.x;
    int f2 = threadIdx.x;
    if (f2 >= KP / 2) return;
    float2 o = (f2 < D / 2) ? ((const float2*)(x + (size_t)e * D))[f2]
                            : make_float2(0.f, 0.f);
    split_store(xh, xl, (size_t)e * KP + 2 * f2, o);
}

// ================= qualifier build -> bf16 split row-major [TOT][KP] =================
__global__ __launch_bounds__(128)
void build_q_k(const float* __restrict__ x, const float* __restrict__ rel,
               const int* __restrict__ qe, const int* __restrict__ qr,
               __nv_bfloat16* __restrict__ qhi, __nv_bfloat16* __restrict__ qlo) {
    int e = blockIdx.x;
    int f2 = threadIdx.x;
    if (f2 >= KP / 2) return;
    float2 o = make_float2(0.f, 0.f);
    if (f2 < D / 2) {
        int e0 = qe[e], e1 = qe[TOT + e];
        int r0 = qr[e], r1 = qr[TOT + e];
        float2 a = ((const float2*)(x + (size_t)e0 * D))[f2];
        float2 b = ((const float2*)(rel + (size_t)r0 * D))[f2];
        float2 c = ((const float2*)(x + (size_t)e1 * D))[f2];
        float2 d = ((const float2*)(rel + (size_t)r1 * D))[f2];
        o.x = a.x * b.x + c.x * d.x;
        o.y = a.y * b.y + c.y * d.y;
    }
    split_store(qhi, qlo, (size_t)e * KP + 2 * f2, o);
}

// ================= wmma qual GEMM (bf16 split) + fused P epilogue =================
constexpr int WMMA_LDC  = 212;
constexpr int WMMA_SMEM = 4 * 16 * WMMA_LDC * 4;     // 54272 bytes

__global__ __launch_bounds__(128, 2)
void wmma_gemm1_k(const __nv_bfloat16* __restrict__ qhi, const __nv_bfloat16* __restrict__ qlo,
                  const __nv_bfloat16* __restrict__ whi, const __nv_bfloat16* __restrict__ wlo,
                  float* __restrict__ P,
                  const int* __restrict__ ei, const int* __restrict__ et,
                  const float* __restrict__ x, const float* __restrict__ rel,
                  const float* __restrict__ nrm) {
    extern __shared__ float csm[];
    const int wid = threadIdx.x >> 5, lid = threadIdx.x & 31;
    const int row0 = blockIdx.x * 64 + wid * 16;

    wmma::fragment<wmma::accumulator, 16, 16, 16, float> c[13];
#pragma unroll
    for (int j = 0; j < 13; j++) wmma::fill_fragment(c[j], 0.f);

    for (int k = 0; k < 13; k++) {
        wmma::fragment<wmma::matrix_a, 16, 16, 16, __nv_bfloat16, wmma::row_major> ah, al;
        wmma::load_matrix_sync(ah, qhi + (size_t)row0 * KP + k * 16, KP);
        wmma::load_matrix_sync(al, qlo + (size_t)row0 * KP + k * 16, KP);
#pragma unroll
        for (int j = 0; j < 13; j++) {
            wmma::fragment<wmma::matrix_b, 16, 16, 16, __nv_bfloat16, wmma::row_major> bh, bl;
            wmma::load_matrix_sync(bh, whi + k * 16 * KP + j * 16, KP);
            wmma::load_matrix_sync(bl, wlo + k * 16 * KP + j * 16, KP);
            wmma::mma_sync(c[j], ah, bh, c[j]);
            wmma::mma_sync(c[j], ah, bl, c[j]);
            wmma::mma_sync(c[j], al, bh, c[j]);
        }
    }

    float* buf = csm + wid * 16 * WMMA_LDC;
#pragma unroll
    for (int j = 0; j < 13; j++)
        wmma::store_matrix_sync(buf + j * 16, c[j], WMMA_LDC, wmma::mem_row_major);
    __syncwarp();

    for (int rr = 0; rr < 16; rr++) {
        int gm = row0 + rr;
        int sI = ei[gm], ev = et[gm];
        float nm = nrm[gm];
        const float4* xr = (const float4*)(x + (size_t)sI * D);
        const float4* rv = (const float4*)(rel + (size_t)ev * D);
        const float4* cb = (const float4*)(buf + rr * WMMA_LDC);
        float4* pp = (float4*)(P + (size_t)gm * D);
        for (int q = lid; q < D / 4; q += 32) {
            float4 acc = cb[q], xx = xr[q], rl = rv[q], o;
            o.x = nm * xx.x * (0.5f * rl.x + 0.5f * acc.x);
            o.y = nm * xx.y * (0.5f * rl.y + 0.5f * acc.y);
            o.z = nm * xx.z * (0.5f * rl.z + 0.5f * acc.z);
            o.w = nm * xx.w * (0.5f * rl.w + 0.5f * acc.w);
            pp[q] = o;
        }
    }
}

// ================= wmma K600 GEMM: agg = Min@w_in + Mout@w_out + x@W2 =================
// 64 rows/block, 4 warps; 3 segments x 13 k-tiles x 13 n-tiles, 3-term bf16 split.
// n-tiles 0..11 stored directly to global (ld=200); tile 12 via smem (cols 192..199).
__global__ __launch_bounds__(128)
void wmma_k600_k(const __nv_bfloat16* __restrict__ mih, const __nv_bfloat16* __restrict__ mil,
                 const __nv_bfloat16* __restrict__ moh, const __nv_bfloat16* __restrict__ mol,
                 const __nv_bfloat16* __restrict__ xh,  const __nv_bfloat16* __restrict__ xl,
                 const __nv_bfloat16* __restrict__ bch, const __nv_bfloat16* __restrict__ bcl,
                 float* __restrict__ agg) {
    __shared__ float sbuf[4][16 * 16];
    const int wid = threadIdx.x >> 5, lid = threadIdx.x & 31;
    const int row0 = blockIdx.x * 64 + wid * 16;

    wmma::fragment<wmma::accumulator, 16, 16, 16, float> c[13];
#pragma unroll
    for (int j = 0; j < 13; j++) wmma::fill_fragment(c[j], 0.f);

#pragma unroll
    for (int seg = 0; seg < 3; seg++) {
        const __nv_bfloat16* ahp = (seg == 0) ? mih : ((seg == 1) ? moh : xh);
        const __nv_bfloat16* alp = (seg == 0) ? mil : ((seg == 1) ? mol : xl);
        for (int k = 0; k < 13; k++) {
            wmma::fragment<wmma::matrix_a, 16, 16, 16, __nv_bfloat16, wmma::row_major> ah, al;
            wmma::load_matrix_sync(ah, ahp + (size_t)row0 * KP + k * 16, KP);
            wmma::load_matrix_sync(al, alp + (size_t)row0 * KP + k * 16, KP);
#pragma unroll
            for (int j = 0; j < 13; j++) {
                wmma::fragment<wmma::matrix_b, 16, 16, 16, __nv_bfloat16, wmma::row_major> bh, bl;
                const __nv_bfloat16* bb = bch + ((size_t)seg * KP + k * 16) * KP + j * 16;
                const __nv_bfloat16* bb2 = bcl + ((size_t)seg * KP + k * 16) * KP + j * 16;
                wmma::load_matrix_sync(bh, bb, KP);
                wmma::load_matrix_sync(bl, bb2, KP);
                wmma::mma_sync(c[j], ah, bh, c[j]);
                wmma::mma_sync(c[j], ah, bl, c[j]);
                wmma::mma_sync(c[j], al, bh, c[j]);
            }
        }
    }

#pragma unroll
    for (int j = 0; j < 12; j++)
        wmma::store_matrix_sync(agg + (size_t)row0 * D + j * 16, c[j], D,
                                wmma::mem_row_major);
    wmma::store_matrix_sync(&sbuf[wid][0], c[12], 16, wmma::mem_row_major);
    __syncwarp();
#pragma unroll
    for (int it = 0; it < 4; it++) {
        int rr = it * 4 + (lid >> 3);
        int cc = lid & 7;
        agg[(size_t)(row0 + rr) * D + 192 + cc] = sbuf[wid][rr * 16 + cc];
    }
}

// ================= FFMA2 SIMT GEMM (rel update only) =================
constexpr int BK = 10, NSTG = 3;

template <int NSEG, int BMT, int NTT, int OCC>
__global__ __launch_bounds__(NTT, OCC)
void gemm_k(const float* A0, const float* A1, const float* A2,
            const float* __restrict__ Bw, float* C, int M) {
    static_assert(BMT == NTT / 2, "geometry");
    __shared__ __align__(16) float As[NSTG][BMT * BK];
    __shared__ __align__(16) float Bs[NSTG][BK * D];

    const int t  = threadIdx.x;
    const int tx = t & 3;
    const int ty = t >> 2;
    const int m0 = blockIdx.x * BMT;
    constexpr int NIT = NSEG * (D / BK);

    uint32_t sA = (uint32_t)__cvta_generic_to_shared(&As[0][0]);
    uint32_t sB = (uint32_t)__cvta_generic_to_shared(&Bs[0][0]);

    auto issue_tile = [&](int tile) {
        int s = tile % NSTG;
        int seg = (NSEG == 1) ? 0 : tile / (D / BK);
        int k0 = tile * BK - seg * D;
        const float* Ause = (NSEG == 1) ? A0
                           : (seg == 0 ? A0 : (seg == 1 ? A1 : A2));
        for (int i = t; i < BMT * BK / 2; i += NTT) {
            int r = i / 5, cc = i - r * 5;
            int gm = m0 + r;
            const float* src = Ause + (size_t)gm * D + k0 + cc * 2;
            int sz = (gm < M) ? 8 : 0;
            asm volatile("cp.async.ca.shared.global [%0], [%1], 8, %2;\n"
                         :: "r"(sA + (uint32_t)((s * BMT * BK + r * BK + cc * 2) * 4)),
                            "l"(src), "r"(sz));
        }
        int kb = tile * BK;
        for (int i = t; i < BK * D / 4; i += NTT) {
            int rr = i / 50, cc = i - rr * 50;
            const float* src = Bw + (size_t)(kb + rr) * D + cc * 4;
            asm volatile("cp.async.ca.shared.global [%0], [%1], 16;\n"
                         :: "r"(sB + (uint32_t)((s * BK * D + rr * D + cc * 4) * 4)),
                            "l"(src));
        }
        asm volatile("cp.async.commit_group;\n");
    };

    issue_tile(0);
    issue_tile(1);

    float2 acc0[25], acc1[25];
#pragma unroll
    for (int j = 0; j < 25; j++) {
        acc0[j] = make_float2(0.f, 0.f);
        acc1[j] = make_float2(0.f, 0.f);
    }

    const int r0 = 2 * ty * BK, r1 = (2 * ty + 1) * BK;
    for (int it = 0; it < NIT; it++) {
        asm volatile("cp.async.wait_group 1;\n");
        __syncthreads();
        const float* as = &As[it % NSTG][0];
        const float* bs = &Bs[it % NSTG][0];
#pragma unroll
        for (int kk = 0; kk < BK; kk += 2) {
            float2 a0 = *(const float2*)(as + r0 + kk);
            float2 a1 = *(const float2*)(as + r1 + kk);
            float2 a00 = make_float2(a0.x, a0.x), a01 = make_float2(a0.y, a0.y);
            float2 a10 = make_float2(a1.x, a1.x), a11 = make_float2(a1.y, a1.y);
            const float2* b0 = (const float2*)(bs + kk * D);
            const float2* b1 = (const float2*)(bs + (kk + 1) * D);
#pragma unroll
            for (int j = 0; j < 25; j++) {
                float2 bv0 = b0[tx + 4 * j];
                float2 bv1 = b1[tx + 4 * j];
                fma2(acc0[j], a00, bv0);
                fma2(acc1[j], a10, bv0);
                fma2(acc0[j], a01, bv1);
                fma2(acc1[j], a11, bv1);
            }
        }
        __syncthreads();
        if (it + 2 < NIT) issue_tile(it + 2);
        else asm volatile("cp.async.commit_group;\n");
    }

#pragma unroll
    for (int rr = 0; rr < 2; rr++) {
        int gm = m0 + 2 * ty + rr;
        if (gm >= M) continue;
        float2* accp = rr ? acc1 : acc0;
        float2* cp = (float2*)(C + (size_t)gm * D);
#pragma unroll
        for (int j = 0; j < 25; j++) cp[tx + 4 * j] = accp[j];
    }
}

// ================= per-dst CSR segment-sum of P -> bf16 split Min/Mout =================
constexpr int AGG_BLOCKS = NE / 2;   // 20000
__global__ __launch_bounds__(256)
void aggregate_k(const float* __restrict__ Pm,
                 const int* __restrict__ off_in, const int* __restrict__ ce_in,
                 const int* __restrict__ off_out, const int* __restrict__ ce_out,
                 __nv_bfloat16* __restrict__ mih, __nv_bfloat16* __restrict__ mil,
                 __nv_bfloat16* __restrict__ moh, __nv_bfloat16* __restrict__ mol) {
    int f2 = threadIdx.x & 127;
    if (f2 >= D / 2) return;
    int r = blockIdx.x * 2 + (threadIdx.x >> 7);

    float2 vi = make_float2(0.f, 0.f);
    int j0 = off_in[r], j1 = off_in[r + 1];
    for (int j = j0; j < j1; j++) {
        float2 m = ((const float2*)(Pm + (size_t)ce_in[j] * D))[f2];
        vi.x += m.x;
        vi.y += m.y;
    }
    split_store(mih, mil, (size_t)r * KP + 2 * f2, vi);

    float2 vo = make_float2(0.f, 0.f);
    j0 = off_out[r]; j1 = off_out[r + 1];
    for (int j = j0; j < j1; j++) {
        float2 m = ((const float2*)(Pm + (size_t)ce_out[j] * D))[f2];
        vo.x += m.x;
        vo.y += m.y;
    }
    split_store(moh, mol, (size_t)r * KP + 2 * f2, vo);
}

// ================= BN =================
constexpr int BN_BLOCKS = 1600, BN_ROWS = NE / BN_BLOCKS;
__global__ __launch_bounds__(128)
void bn_stats_k(const float* __restrict__ t, float* __restrict__ sum,
                float* __restrict__ sumsq) {
    int f2 = threadIdx.x;
    if (f2 >= D / 2) return;
    int r0 = blockIdx.x * BN_ROWS;
    float sx = 0.f, sy = 0.f, qx = 0.f, qy = 0.f;
    for (int r = r0; r < r0 + BN_ROWS; r++) {
        float2 v = ((const float2*)(t + (size_t)r * D))[f2];
        sx += v.x; sy += v.y;
        qx += v.x * v.x; qy += v.y * v.y;
    }
    atomicAdd(&sum[2 * f2], sx);
    atomicAdd(&sum[2 * f2 + 1], sy);
    atomicAdd(&sumsq[2 * f2], qx);
    atomicAdd(&sumsq[2 * f2 + 1], qy);
}

__global__ void bn_final_k(const float* __restrict__ sum, const float* __restrict__ sumsq,
                           const float* __restrict__ gamma, const float* __restrict__ beta,
                           float* __restrict__ cA, float* __restrict__ cB) {
    int f = threadIdx.x;
    if (f >= D) return;
    float mean = sum[f] * (1.f / NE);
    float var  = sumsq[f] * (1.f / NE) - mean * mean;
    if (var < 0.f) var = 0.f;
    float rs = rsqrtf(var * (1.f / 9.f) + EPSV);
    float a  = gamma[f] * rs * (1.f / 3.f);
    cA[f] = a;
    cB[f] = beta[f] - a * mean;
}

template <bool EMIT_SPLIT>
__global__ void bn_apply_k(const float* __restrict__ t, const float* __restrict__ cA,
                           const float* __restrict__ cB, float* __restrict__ xo,
                           __nv_bfloat16* __restrict__ xh, __nv_bfloat16* __restrict__ xl) {
    int i = blockIdx.x * blockDim.x + threadIdx.x;
    if (i < NE * D / 2) {
        int f2 = i % (D / 2);
        float2 v = ((const float2*)t)[i];
        float2 o;
        o.x = tanhf(cA[2 * f2] * v.x + cB[2 * f2]);
        o.y = tanhf(cA[2 * f2 + 1] * v.y + cB[2 * f2 + 1]);
        ((float2*)xo)[i] = o;
        if (EMIT_SPLIT) {
            int row = i / (D / 2);
            split_store(xh, xl, (size_t)row * KP + 2 * f2, o);
        }
    }
}

// ================= output gathers =================
__global__ void gather_k(const float* __restrict__ src, const int* __restrict__ idx,
                         float* __restrict__ out) {
    int b = blockIdx.x;
    int f = threadIdx.x;
    if (f < D / 2) {
        ((float2*)(out + (size_t)b * D))[f] =
            ((const float2*)(src + (size_t)idx[b] * D))[f];
    }
}

// ================= driver =================
extern "C" void kernel_launch(void* const* d_in, const int* in_sizes, int n_in,
                              void* d_out, int out_size) {
    const int* ei  = (const int*)d_in[0];
    const int* et  = (const int*)d_in[1];
    const int* qe  = (const int*)d_in[2];
    const int* qr  = (const int*)d_in[3];
    const int* sub = (const int*)d_in[4];
    const int* rel = (const int*)d_in[5];
    const float* init_embed = (const float*)d_in[6];
    const float* init_rel   = (const float*)d_in[7];
    const float* L[2][9];
    for (int l = 0; l < 2; l++)
        for (int p = 0; p < 9; p++) L[l][p] = (const float*)d_in[8 + l * 9 + p];

    float *deg, *nrm, *relbuf, *r1, *r2, *P, *agg, *x1, *sum, *sumsq, *cA, *cB;
    __nv_bfloat16 *qhi, *qlo, *whi, *wlo, *mih, *mil, *moh, *mol, *xh, *xl, *bch, *bcl;
    int *cin, *cout, *oin, *oout, *curin, *curout, *cein, *ceout;
    cudaGetSymbolAddress((void**)&deg,    g_deg);
    cudaGetSymbolAddress((void**)&nrm,    g_norm);
    cudaGetSymbolAddress((void**)&cin,    g_cnt_in);
    cudaGetSymbolAddress((void**)&cout,   g_cnt_out);
    cudaGetSymbolAddress((void**)&oin,    g_off_in);
    cudaGetSymbolAddress((void**)&oout,   g_off_out);
    cudaGetSymbolAddress((void**)&curin,  g_cur_in);
    cudaGetSymbolAddress((void**)&curout, g_cur_out);
    cudaGetSymbolAddress((void**)&cein,   g_ce_in);
    cudaGetSymbolAddress((void**)&ceout,  g_ce_out);
    cudaGetSymbolAddress((void**)&relbuf, g_relbuf);
    cudaGetSymbolAddress((void**)&r1,     g_r1);
    cudaGetSymbolAddress((void**)&r2,     g_r2);
    cudaGetSymbolAddress((void**)&qhi,    g_Qhi);
    cudaGetSymbolAddress((void**)&qlo,    g_Qlo);
    cudaGetSymbolAddress((void**)&whi,    g_Whi);
    cudaGetSymbolAddress((void**)&wlo,    g_Wlo);
    cudaGetSymbolAddress((void**)&mih,    g_Mih);
    cudaGetSymbolAddress((void**)&mil,    g_Mil);
    cudaGetSymbolAddress((void**)&moh,    g_Moh);
    cudaGetSymbolAddress((void**)&mol,    g_Mol);
    cudaGetSymbolAddress((void**)&xh,     g_Xhi);
    cudaGetSymbolAddress((void**)&xl,     g_Xlo);
    cudaGetSymbolAddress((void**)&bch,    g_BChi);
    cudaGetSymbolAddress((void**)&bcl,    g_BClo);
    cudaGetSymbolAddress((void**)&P,      g_P);
    cudaGetSymbolAddress((void**)&agg,    g_agg);
    cudaGetSymbolAddress((void**)&x1,     g_x1);
    cudaGetSymbolAddress((void**)&sum,    g_sum);
    cudaGetSymbolAddress((void**)&sumsq,  g_sumsq);
    cudaGetSymbolAddress((void**)&cA,     g_cA);
    cudaGetSymbolAddress((void**)&cB,     g_cB);

    static int smem_set = 0;
    if (!smem_set) {
        cudaFuncSetAttribute(wmma_gemm1_k, cudaFuncAttributeMaxDynamicSharedMemorySize,
                             WMMA_SMEM);
        smem_set = 1;
    }

    float* out     = (float*)d_out;
    float* out_sub = out;
    float* out_rel = out + NB * D;
    float* out_x   = out + 2 * NB * D;

    // graph structure (layer-invariant)
    cudaMemsetAsync(deg, 0, 2 * NE * sizeof(float));
    cudaMemsetAsync(cin, 0, NE * sizeof(int));
    cudaMemsetAsync(cout, 0, NE * sizeof(int));
    degcnt_k<<<(TOT + 255) / 256, 256>>>(ei, deg, cin, cout);
    norm_k<<<(TOT + 255) / 256, 256>>>(ei, deg, nrm);
    scan2_k<<<2, SCAN_T>>>(cin, oin, curin, cout, oout, curout);
    fill_k<<<(TOT + 255) / 256, 256>>>(ei, curin, curout, cein, ceout);
    // x bf16 split for layer 1
    conv_x_k<<<NE, 128>>>(init_embed, xh, xl);

    for (int l = 0; l < 2; l++) {
        const float* x_in = l ? x1 : init_embed;
        const float* r_in = l ? r1 : init_rel;
        float* x_out = l ? out_x : x1;
        float* r_out = l ? r2 : r1;

        cudaMemcpyAsync(relbuf, r_in, R2 * D * sizeof(float), cudaMemcpyDeviceToDevice);
        cudaMemcpyAsync(relbuf + R2 * D, L[l][5], D * sizeof(float), cudaMemcpyDeviceToDevice);
        cudaMemsetAsync(sum, 0, D * sizeof(float));
        cudaMemsetAsync(sumsq, 0, D * sizeof(float));

        prep_bcat_split_k<<<(3 * KP * KP + 255) / 256, 256>>>(L[l][1], L[l][2], L[l][0],
                                                              L[l][5], bch, bcl);
        prep_wimg_k<<<(KP * KP + 255) / 256, 256>>>(L[l][4], whi, wlo);
        build_q_k<<<TOT, 128>>>(x_in, relbuf, qe, qr, qhi, qlo);
        // tensor-core qual GEMM + fused P epilogue
        wmma_gemm1_k<<<TOT / 64, 128, WMMA_SMEM>>>(qhi, qlo, whi, wlo, P, ei, et,
                                                   x_in, relbuf, nrm);
        // per-dst segment sums of P -> bf16 split Min/Mout
        aggregate_k<<<AGG_BLOCKS, 256>>>(P, oin, cein, oout, ceout, mih, mil, moh, mol);
        // tensor-core K600 GEMM: agg = Min@w_in + Mout@w_out + x@W2
        wmma_k600_k<<<NE / 64, 128>>>(mih, mil, moh, mol, xh, xl, bch, bcl, agg);
        // BN + tanh (layer 1 also emits x1 bf16 split for next layer)
        bn_stats_k<<<BN_BLOCKS, 128>>>(agg, sum, sumsq);
        bn_final_k<<<1, 224>>>(sum, sumsq, L[l][7], L[l][8], cA, cB);
        if (l == 0)
            bn_apply_k<true><<<(NE * D / 2 + 255) / 256, 256>>>(agg, cA, cB, x_out, xh, xl);
        else
            bn_apply_k<false><<<(NE * D / 2 + 255) / 256, 256>>>(agg, cA, cB, x_out,
                                                                 nullptr, nullptr);
        // rel update (tiny, FFMA2 path)
        gemm_k<1, 128, 256, 2><<<(R2 + 127) / 128, 256>>>(r_in, nullptr, nullptr,
                                                          L[l][3], r_out, R2);
    }

    gather_k<<<NB, 128>>>(out_x, sub, out_sub);
    gather_k<<<NB, 128>>>(r2, rel, out_rel);
}

// round 16
// speedup vs baseline: 2.4808x; 1.1837x over previous
#include <cuda_runtime.h>
#include <cuda_bf16.h>
#include <mma.h>
#include <math.h>
#include <stdint.h>

using namespace nvcuda;

#define D      200
#define KP     208          // K and N padded to 13*16 for wmma
#define NE     40000
#define TOT    160000
#define EHALF  80000
#define R2     200
#define NB     1024
#define EPSV   1e-5f

// ================= scratch (static device globals; no allocation) =================
__device__ float g_deg[2 * NE];
__device__ float g_norm[TOT];
__device__ int   g_cnt_in[NE], g_cnt_out[NE];
__device__ int   g_off_in[NE + 1], g_off_out[NE + 1];
__device__ int   g_cur_in[NE], g_cur_out[NE];
__device__ int   g_ce_in[EHALF], g_ce_out[EHALF];
__device__ float g_relbuf[(R2 + 1) * D];
__device__ float g_r1[R2 * D];
__device__ float g_r2[R2 * D];
__device__ __align__(256) __nv_bfloat16 g_Qhi[(size_t)TOT * KP];
__device__ __align__(256) __nv_bfloat16 g_Qlo[(size_t)TOT * KP];
__device__ __align__(256) __nv_bfloat16 g_Whi[KP * KP];
__device__ __align__(256) __nv_bfloat16 g_Wlo[KP * KP];
// K600 operands (bf16 split, zero-padded; pads never written => stay zero)
__device__ __align__(256) __nv_bfloat16 g_Mih[(size_t)NE * KP];
__device__ __align__(256) __nv_bfloat16 g_Mil[(size_t)NE * KP];
__device__ __align__(256) __nv_bfloat16 g_Moh[(size_t)NE * KP];
__device__ __align__(256) __nv_bfloat16 g_Mol[(size_t)NE * KP];
__device__ __align__(256) __nv_bfloat16 g_Xhi[(size_t)NE * KP];
__device__ __align__(256) __nv_bfloat16 g_Xlo[(size_t)NE * KP];
__device__ __align__(256) __nv_bfloat16 g_BChi[3 * KP * KP];
__device__ __align__(256) __nv_bfloat16 g_BClo[3 * KP * KP];
__device__ __align__(256) float g_P[(size_t)TOT * D];
__device__ __align__(256) float g_agg[NE * D];
__device__ __align__(256) float g_x1[NE * D];
__device__ float g_sum[D], g_sumsq[D], g_cA[D], g_cB[D];

// packed f32x2 FMA (sm_103a FFMA2 — PTX only)
__device__ __forceinline__ void fma2(float2& c, float2 a, float2 b) {
    unsigned long long cc = *reinterpret_cast<const unsigned long long*>(&c);
    unsigned long long aa = *reinterpret_cast<const unsigned long long*>(&a);
    unsigned long long bb = *reinterpret_cast<const unsigned long long*>(&b);
    asm("fma.rn.f32x2 %0, %1, %2, %0;" : "+l"(cc) : "l"(aa), "l"(bb));
    c = *reinterpret_cast<float2*>(&cc);
}

__device__ __forceinline__ void split_store(__nv_bfloat16* hi, __nv_bfloat16* lo,
                                            size_t off, float2 o) {
    __nv_bfloat16 hx = __float2bfloat16(o.x), hy = __float2bfloat16(o.y);
    __nv_bfloat162 hv; hv.x = hx; hv.y = hy;
    __nv_bfloat162 lv;
    lv.x = __float2bfloat16(o.x - __bfloat162float(hx));
    lv.y = __float2bfloat16(o.y - __bfloat162float(hy));
    *(__nv_bfloat162*)(hi + off) = hv;
    *(__nv_bfloat162*)(lo + off) = lv;
}

// ================= graph preprocessing =================
__global__ void degcnt_k(const int* __restrict__ ei, float* __restrict__ deg,
                         int* __restrict__ cin, int* __restrict__ cout) {
    int i = blockIdx.x * blockDim.x + threadIdx.x;
    if (i < TOT) {
        int off = (i >= EHALF) ? NE : 0;
        atomicAdd(&deg[off + ei[i]], 1.0f);
        int dst = ei[TOT + i];
        if (i < EHALF) atomicAdd(&cin[dst], 1);
        else           atomicAdd(&cout[dst], 1);
    }
}

__global__ void norm_k(const int* __restrict__ ei, const float* __restrict__ deg,
                       float* __restrict__ nrm) {
    int i = blockIdx.x * blockDim.x + threadIdx.x;
    if (i < TOT) {
        int off = (i >= EHALF) ? NE : 0;
        float a = deg[off + ei[i]];
        float b = deg[off + ei[TOT + i]];
        float va = (a > 0.f) ? rsqrtf(a) : 0.f;
        float vb = (b > 0.f) ? rsqrtf(b) : 0.f;
        nrm[i] = va * vb;
    }
}

#define SCAN_T 1024
__global__ void scan2_k(const int* __restrict__ cnt_in, int* __restrict__ off_in,
                        int* __restrict__ cur_in,
                        const int* __restrict__ cnt_out, int* __restrict__ off_out,
                        int* __restrict__ cur_out) {
    const int* cnt = blockIdx.x ? cnt_out : cnt_in;
    int* off       = blockIdx.x ? off_out : off_in;
    int* cur       = blockIdx.x ? cur_out : cur_in;
    __shared__ int part[SCAN_T];
    int t = threadIdx.x;
    const int CH = (NE + SCAN_T - 1) / SCAN_T;
    int base = t * CH;
    int s = 0;
    for (int i = 0; i < CH; i++) {
        int idx = base + i;
        if (idx < NE) s += cnt[idx];
    }
    part[t] = s;
    __syncthreads();
    for (int d = 1; d < SCAN_T; d <<= 1) {
        int v = (t >= d) ? part[t - d] : 0;
        __syncthreads();
        part[t] += v;
        __syncthreads();
    }
    int run = (t > 0) ? part[t - 1] : 0;
    for (int i = 0; i < CH; i++) {
        int idx = base + i;
        if (idx < NE) {
            off[idx] = run;
            cur[idx] = run;
            run += cnt[idx];
        }
    }
    if (t == SCAN_T - 1) off[NE] = EHALF;
}

__global__ void fill_k(const int* __restrict__ ei, int* __restrict__ cur_in,
                       int* __restrict__ cur_out, int* __restrict__ ce_in,
                       int* __restrict__ ce_out) {
    int e = blockIdx.x * blockDim.x + threadIdx.x;
    if (e < TOT) {
        int dst = ei[TOT + e];
        if (e < EHALF) { int p = atomicAdd(&cur_in[dst], 1);  ce_in[p] = e; }
        else           { int p = atomicAdd(&cur_out[dst], 1); ce_out[p] = e; }
    }
}

// ================= weight prep =================
__global__ void prep_bcat_split_k(const float* __restrict__ w_in,
                                  const float* __restrict__ w_out,
                                  const float* __restrict__ w_loop,
                                  const float* __restrict__ lr,
                                  __nv_bfloat16* __restrict__ bh,
                                  __nv_bfloat16* __restrict__ bl) {
    int i = blockIdx.x * blockDim.x + threadIdx.x;
    if (i >= 3 * KP * KP) return;
    int s = i / (KP * KP);
    int rem = i - s * (KP * KP);
    int k = rem / KP, n = rem - k * KP;
    float v = 0.f;
    if (k < D && n < D) {
        if (s == 0)      v = w_in[k * D + n];
        else if (s == 1) v = w_out[k * D + n];
        else             v = lr[k] * w_loop[k * D + n];
    }
    __nv_bfloat16 h = __float2bfloat16(v);
    bh[i] = h;
    bl[i] = __float2bfloat16(v - __bfloat162float(h));
}

__global__ void prep_wimg_k(const float* __restrict__ W,
                            __nv_bfloat16* __restrict__ hi, __nv_bfloat16* __restrict__ lo) {
    int i = blockIdx.x * blockDim.x + threadIdx.x;
    if (i >= KP * KP) return;
    int k = i / KP, n = i - k * KP;
    float v = (k < D && n < D) ? W[k * D + n] : 0.f;
    __nv_bfloat16 h = __float2bfloat16(v);
    hi[i] = h;
    lo[i] = __float2bfloat16(v - __bfloat162float(h));
}

// x fp32 [NE][D] -> bf16 split [NE][KP]
__global__ __launch_bounds__(128)
void conv_x_k(const float* __restrict__ x,
              __nv_bfloat16* __restrict__ xh, __nv_bfloat16* __restrict__ xl) {
    int e = blockIdx.x;
    int f2 = threadIdx.x;
    if (f2 >= KP / 2) return;
    float2 o = (f2 < D / 2) ? ((const float2*)(x + (size_t)e * D))[f2]
                            : make_float2(0.f, 0.f);
    split_store(xh, xl, (size_t)e * KP + 2 * f2, o);
}

// ================= qualifier build -> bf16 split row-major [TOT][KP] =================
__global__ __launch_bounds__(128)
void build_q_k(const float* __restrict__ x, const float* __restrict__ rel,
               const int* __restrict__ qe, const int* __restrict__ qr,
               __nv_bfloat16* __restrict__ qhi, __nv_bfloat16* __restrict__ qlo) {
    int e = blockIdx.x;
    int f2 = threadIdx.x;
    if (f2 >= KP / 2) return;
    float2 o = make_float2(0.f, 0.f);
    if (f2 < D / 2) {
        int e0 = qe[e], e1 = qe[TOT + e];
        int r0 = qr[e], r1 = qr[TOT + e];
        float2 a = ((const float2*)(x + (size_t)e0 * D))[f2];
        float2 b = ((const float2*)(rel + (size_t)r0 * D))[f2];
        float2 c = ((const float2*)(x + (size_t)e1 * D))[f2];
        float2 d = ((const float2*)(rel + (size_t)r1 * D))[f2];
        o.x = a.x * b.x + c.x * d.x;
        o.y = a.y * b.y + c.y * d.y;
    }
    split_store(qhi, qlo, (size_t)e * KP + 2 * f2, o);
}

// ================= persistent wmma GEMM, W staged in smem =================
// MODE 0: C[tile] = acc (store)                  — K600 pass 0
// MODE 1: C[tile] += acc (acc-init from C)       — K600 passes 1,2
// MODE 2: P epilogue: P = nrm*x[src]*(0.5*rel[et]+0.5*acc)
constexpr int WBYTES    = KP * KP * 2;                 // 86528 per matrix
constexpr int PW_SMEM   = 2 * WBYTES + 8 * 256 * 4;    // W hi+lo + 8 warp bufs = 181248

template <int MODE>
__global__ __launch_bounds__(256, 1)
void pwmma_k(const __nv_bfloat16* __restrict__ ahg, const __nv_bfloat16* __restrict__ alg,
             const __nv_bfloat16* __restrict__ whg, const __nv_bfloat16* __restrict__ wlg,
             float* __restrict__ C, int M,
             const int* __restrict__ ei, const int* __restrict__ et,
             const float* __restrict__ x, const float* __restrict__ rel,
             const float* __restrict__ nrm) {
    extern __shared__ __align__(256) char smem[];
    __nv_bfloat16* sWhi = (__nv_bfloat16*)smem;
    __nv_bfloat16* sWlo = (__nv_bfloat16*)(smem + WBYTES);
    float* wbufs = (float*)(smem + 2 * WBYTES);

    const int tid = threadIdx.x, wid = tid >> 5, lid = tid & 31;

    // stage W hi+lo into smem
    {
        uint32_t s0 = (uint32_t)__cvta_generic_to_shared(smem);
        const char* h = (const char*)whg;
        const char* l = (const char*)wlg;
        for (int i = tid * 16; i < WBYTES; i += 256 * 16) {
            asm volatile("cp.async.ca.shared.global [%0], [%1], 16;\n"
                         :: "r"(s0 + i), "l"(h + i));
            asm volatile("cp.async.ca.shared.global [%0], [%1], 16;\n"
                         :: "r"(s0 + WBYTES + i), "l"(l + i));
        }
        asm volatile("cp.async.commit_group;\n");
        asm volatile("cp.async.wait_group 0;\n");
        __syncthreads();
    }

    const int ntiles = M / 16;
    const int stride = gridDim.x * 8;
    float* wb = wbufs + wid * 256;
    const int r = lid >> 1, h = lid & 1;

    for (int tile = blockIdx.x * 8 + wid; tile < ntiles; tile += stride) {
        const int row0 = tile * 16;

        wmma::fragment<wmma::accumulator, 16, 16, 16, float> c[13];
        if (MODE == 1) {
#pragma unroll
            for (int j = 0; j < 12; j++)
                wmma::load_matrix_sync(c[j], C + (size_t)row0 * D + j * 16, D,
                                       wmma::mem_row_major);
            wmma::fill_fragment(c[12], 0.f);
        } else {
#pragma unroll
            for (int j = 0; j < 13; j++) wmma::fill_fragment(c[j], 0.f);
        }

        for (int k = 0; k < 13; k++) {
            wmma::fragment<wmma::matrix_a, 16, 16, 16, __nv_bfloat16, wmma::row_major> ah, al;
            wmma::load_matrix_sync(ah, ahg + (size_t)row0 * KP + k * 16, KP);
            wmma::load_matrix_sync(al, alg + (size_t)row0 * KP + k * 16, KP);
#pragma unroll
            for (int j = 0; j < 13; j++) {
                wmma::fragment<wmma::matrix_b, 16, 16, 16, __nv_bfloat16, wmma::row_major> bh, bl;
                wmma::load_matrix_sync(bh, sWhi + k * 16 * KP + j * 16, KP);
                wmma::load_matrix_sync(bl, sWlo + k * 16 * KP + j * 16, KP);
                wmma::mma_sync(c[j], ah, bh, c[j]);
                wmma::mma_sync(c[j], ah, bl, c[j]);
                wmma::mma_sync(c[j], al, bh, c[j]);
            }
        }

        if (MODE == 2) {
            int gm = row0 + r;
            int sI = ei[gm], ev = et[gm];
            float nm = nrm[gm];
            const float* xr = x + (size_t)sI * D;
            const float* rv = rel + (size_t)ev * D;
            float* pp = C + (size_t)gm * D;
#pragma unroll
            for (int j = 0; j < 13; j++) {
                wmma::store_matrix_sync(wb, c[j], 16, wmma::mem_row_major);
                __syncwarp();
                int col = j * 16 + h * 8;
                if (col < D) {
                    float4 a0 = *(const float4*)(wb + r * 16 + h * 8);
                    float4 a1 = *(const float4*)(wb + r * 16 + h * 8 + 4);
                    float4 x0 = *(const float4*)(xr + col);
                    float4 x1 = *(const float4*)(xr + col + 4);
                    float4 r0v = *(const float4*)(rv + col);
                    float4 r1v = *(const float4*)(rv + col + 4);
                    float4 o0, o1;
                    o0.x = nm * x0.x * (0.5f * r0v.x + 0.5f * a0.x);
                    o0.y = nm * x0.y * (0.5f * r0v.y + 0.5f * a0.y);
                    o0.z = nm * x0.z * (0.5f * r0v.z + 0.5f * a0.z);
                    o0.w = nm * x0.w * (0.5f * r0v.w + 0.5f * a0.w);
                    o1.x = nm * x1.x * (0.5f * r1v.x + 0.5f * a1.x);
                    o1.y = nm * x1.y * (0.5f * r1v.y + 0.5f * a1.y);
                    o1.z = nm * x1.z * (0.5f * r1v.z + 0.5f * a1.z);
                    o1.w = nm * x1.w * (0.5f * r1v.w + 0.5f * a1.w);
                    *(float4*)(pp + col) = o0;
                    *(float4*)(pp + col + 4) = o1;
                }
                __syncwarp();
            }
        } else {
#pragma unroll
            for (int j = 0; j < 12; j++)
                wmma::store_matrix_sync(C + (size_t)row0 * D + j * 16, c[j], D,
                                        wmma::mem_row_major);
            wmma::store_matrix_sync(wb, c[12], 16, wmma::mem_row_major);
            __syncwarp();
            // cols 192..199 (tile cols 0..7); each lane: row r, 4 cols
            float* cp = C + (size_t)(row0 + r) * D + 192 + h * 4;
            float4 v = *(const float4*)(wb + r * 16 + h * 4);
            if (MODE == 1) {
                float4 old = *(const float4*)cp;
                v.x += old.x; v.y += old.y; v.z += old.z; v.w += old.w;
            }
            *(float4*)cp = v;
            __syncwarp();
        }
    }
}

// ================= FFMA2 SIMT GEMM (rel update only) =================
constexpr int BK = 10, NSTG = 3;

template <int NSEG, int BMT, int NTT, int OCC>
__global__ __launch_bounds__(NTT, OCC)
void gemm_k(const float* A0, const float* A1, const float* A2,
            const float* __restrict__ Bw, float* C, int M) {
    static_assert(BMT == NTT / 2, "geometry");
    __shared__ __align__(16) float As[NSTG][BMT * BK];
    __shared__ __align__(16) float Bs[NSTG][BK * D];

    const int t  = threadIdx.x;
    const int tx = t & 3;
    const int ty = t >> 2;
    const int m0 = blockIdx.x * BMT;
    constexpr int NIT = NSEG * (D / BK);

    uint32_t sA = (uint32_t)__cvta_generic_to_shared(&As[0][0]);
    uint32_t sB = (uint32_t)__cvta_generic_to_shared(&Bs[0][0]);

    auto issue_tile = [&](int tile) {
        int s = tile % NSTG;
        int seg = (NSEG == 1) ? 0 : tile / (D / BK);
        int k0 = tile * BK - seg * D;
        const float* Ause = (NSEG == 1) ? A0
                           : (seg == 0 ? A0 : (seg == 1 ? A1 : A2));
        for (int i = t; i < BMT * BK / 2; i += NTT) {
            int r = i / 5, cc = i - r * 5;
            int gm = m0 + r;
            const float* src = Ause + (size_t)gm * D + k0 + cc * 2;
            int sz = (gm < M) ? 8 : 0;
            asm volatile("cp.async.ca.shared.global [%0], [%1], 8, %2;\n"
                         :: "r"(sA + (uint32_t)((s * BMT * BK + r * BK + cc * 2) * 4)),
                            "l"(src), "r"(sz));
        }
        int kb = tile * BK;
        for (int i = t; i < BK * D / 4; i += NTT) {
            int rr = i / 50, cc = i - rr * 50;
            const float* src = Bw + (size_t)(kb + rr) * D + cc * 4;
            asm volatile("cp.async.ca.shared.global [%0], [%1], 16;\n"
                         :: "r"(sB + (uint32_t)((s * BK * D + rr * D + cc * 4) * 4)),
                            "l"(src));
        }
        asm volatile("cp.async.commit_group;\n");
    };

    issue_tile(0);
    issue_tile(1);

    float2 acc0[25], acc1[25];
#pragma unroll
    for (int j = 0; j < 25; j++) {
        acc0[j] = make_float2(0.f, 0.f);
        acc1[j] = make_float2(0.f, 0.f);
    }

    const int r0 = 2 * ty * BK, r1 = (2 * ty + 1) * BK;
    for (int it = 0; it < NIT; it++) {
        asm volatile("cp.async.wait_group 1;\n");
        __syncthreads();
        const float* as = &As[it % NSTG][0];
        const float* bs = &Bs[it % NSTG][0];
#pragma unroll
        for (int kk = 0; kk < BK; kk += 2) {
            float2 a0 = *(const float2*)(as + r0 + kk);
            float2 a1 = *(const float2*)(as + r1 + kk);
            float2 a00 = make_float2(a0.x, a0.x), a01 = make_float2(a0.y, a0.y);
            float2 a10 = make_float2(a1.x, a1.x), a11 = make_float2(a1.y, a1.y);
            const float2* b0 = (const float2*)(bs + kk * D);
            const float2* b1 = (const float2*)(bs + (kk + 1) * D);
#pragma unroll
            for (int j = 0; j < 25; j++) {
                float2 bv0 = b0[tx + 4 * j];
                float2 bv1 = b1[tx + 4 * j];
                fma2(acc0[j], a00, bv0);
                fma2(acc1[j], a10, bv0);
                fma2(acc0[j], a01, bv1);
                fma2(acc1[j], a11, bv1);
            }
        }
        __syncthreads();
        if (it + 2 < NIT) issue_tile(it + 2);
        else asm volatile("cp.async.commit_group;\n");
    }

#pragma unroll
    for (int rr = 0; rr < 2; rr++) {
        int gm = m0 + 2 * ty + rr;
        if (gm >= M) continue;
        float2* accp = rr ? acc1 : acc0;
        float2* cp = (float2*)(C + (size_t)gm * D);
#pragma unroll
        for (int j = 0; j < 25; j++) cp[tx + 4 * j] = accp[j];
    }
}

// ================= per-dst CSR segment-sum of P -> bf16 split Min/Mout =================
constexpr int AGG_BLOCKS = NE / 2;   // 20000
__global__ __launch_bounds__(256)
void aggregate_k(const float* __restrict__ Pm,
                 const int* __restrict__ off_in, const int* __restrict__ ce_in,
                 const int* __restrict__ off_out, const int* __restrict__ ce_out,
                 __nv_bfloat16* __restrict__ mih, __nv_bfloat16* __restrict__ mil,
                 __nv_bfloat16* __restrict__ moh, __nv_bfloat16* __restrict__ mol) {
    int f2 = threadIdx.x & 127;
    if (f2 >= D / 2) return;
    int r = blockIdx.x * 2 + (threadIdx.x >> 7);

    float2 vi = make_float2(0.f, 0.f);
    int j0 = off_in[r], j1 = off_in[r + 1];
    for (int j = j0; j < j1; j++) {
        float2 m = ((const float2*)(Pm + (size_t)ce_in[j] * D))[f2];
        vi.x += m.x;
        vi.y += m.y;
    }
    split_store(mih, mil, (size_t)r * KP + 2 * f2, vi);

    float2 vo = make_float2(0.f, 0.f);
    j0 = off_out[r]; j1 = off_out[r + 1];
    for (int j = j0; j < j1; j++) {
        float2 m = ((const float2*)(Pm + (size_t)ce_out[j] * D))[f2];
        vo.x += m.x;
        vo.y += m.y;
    }
    split_store(moh, mol, (size_t)r * KP + 2 * f2, vo);
}

// ================= BN =================
constexpr int BN_BLOCKS = 1600, BN_ROWS = NE / BN_BLOCKS;
__global__ __launch_bounds__(128)
void bn_stats_k(const float* __restrict__ t, float* __restrict__ sum,
                float* __restrict__ sumsq) {
    int f2 = threadIdx.x;
    if (f2 >= D / 2) return;
    int r0 = blockIdx.x * BN_ROWS;
    float sx = 0.f, sy = 0.f, qx = 0.f, qy = 0.f;
    for (int r = r0; r < r0 + BN_ROWS; r++) {
        float2 v = ((const float2*)(t + (size_t)r * D))[f2];
        sx += v.x; sy += v.y;
        qx += v.x * v.x; qy += v.y * v.y;
    }
    atomicAdd(&sum[2 * f2], sx);
    atomicAdd(&sum[2 * f2 + 1], sy);
    atomicAdd(&sumsq[2 * f2], qx);
    atomicAdd(&sumsq[2 * f2 + 1], qy);
}

__global__ void bn_final_k(const float* __restrict__ sum, const float* __restrict__ sumsq,
                           const float* __restrict__ gamma, const float* __restrict__ beta,
                           float* __restrict__ cA, float* __restrict__ cB) {
    int f = threadIdx.x;
    if (f >= D) return;
    float mean = sum[f] * (1.f / NE);
    float var  = sumsq[f] * (1.f / NE) - mean * mean;
    if (var < 0.f) var = 0.f;
    float rs = rsqrtf(var * (1.f / 9.f) + EPSV);
    float a  = gamma[f] * rs * (1.f / 3.f);
    cA[f] = a;
    cB[f] = beta[f] - a * mean;
}

template <bool EMIT_SPLIT>
__global__ void bn_apply_k(const float* __restrict__ t, const float* __restrict__ cA,
                           const float* __restrict__ cB, float* __restrict__ xo,
                           __nv_bfloat16* __restrict__ xh, __nv_bfloat16* __restrict__ xl) {
    int i = blockIdx.x * blockDim.x + threadIdx.x;
    if (i < NE * D / 2) {
        int f2 = i % (D / 2);
        float2 v = ((const float2*)t)[i];
        float2 o;
        o.x = tanhf(cA[2 * f2] * v.x + cB[2 * f2]);
        o.y = tanhf(cA[2 * f2 + 1] * v.y + cB[2 * f2 + 1]);
        ((float2*)xo)[i] = o;
        if (EMIT_SPLIT) {
            int row = i / (D / 2);
            split_store(xh, xl, (size_t)row * KP + 2 * f2, o);
        }
    }
}

// ================= output gathers =================
__global__ void gather_k(const float* __restrict__ src, const int* __restrict__ idx,
                         float* __restrict__ out) {
    int b = blockIdx.x;
    int f = threadIdx.x;
    if (f < D / 2) {
        ((float2*)(out + (size_t)b * D))[f] =
            ((const float2*)(src + (size_t)idx[b] * D))[f];
    }
}

// ================= driver =================
extern "C" void kernel_launch(void* const* d_in, const int* in_sizes, int n_in,
                              void* d_out, int out_size) {
    const int* ei  = (const int*)d_in[0];
    const int* et  = (const int*)d_in[1];
    const int* qe  = (const int*)d_in[2];
    const int* qr  = (const int*)d_in[3];
    const int* sub = (const int*)d_in[4];
    const int* rel = (const int*)d_in[5];
    const float* init_embed = (const float*)d_in[6];
    const float* init_rel   = (const float*)d_in[7];
    const float* L[2][9];
    for (int l = 0; l < 2; l++)
        for (int p = 0; p < 9; p++) L[l][p] = (const float*)d_in[8 + l * 9 + p];

    float *deg, *nrm, *relbuf, *r1, *r2, *P, *agg, *x1, *sum, *sumsq, *cA, *cB;
    __nv_bfloat16 *qhi, *qlo, *whi, *wlo, *mih, *mil, *moh, *mol, *xh, *xl, *bch, *bcl;
    int *cin, *cout, *oin, *oout, *curin, *curout, *cein, *ceout;
    cudaGetSymbolAddress((void**)&deg,    g_deg);
    cudaGetSymbolAddress((void**)&nrm,    g_norm);
    cudaGetSymbolAddress((void**)&cin,    g_cnt_in);
    cudaGetSymbolAddress((void**)&cout,   g_cnt_out);
    cudaGetSymbolAddress((void**)&oin,    g_off_in);
    cudaGetSymbolAddress((void**)&oout,   g_off_out);
    cudaGetSymbolAddress((void**)&curin,  g_cur_in);
    cudaGetSymbolAddress((void**)&curout, g_cur_out);
    cudaGetSymbolAddress((void**)&cein,   g_ce_in);
    cudaGetSymbolAddress((void**)&ceout,  g_ce_out);
    cudaGetSymbolAddress((void**)&relbuf, g_relbuf);
    cudaGetSymbolAddress((void**)&r1,     g_r1);
    cudaGetSymbolAddress((void**)&r2,     g_r2);
    cudaGetSymbolAddress((void**)&qhi,    g_Qhi);
    cudaGetSymbolAddress((void**)&qlo,    g_Qlo);
    cudaGetSymbolAddress((void**)&whi,    g_Whi);
    cudaGetSymbolAddress((void**)&wlo,    g_Wlo);
    cudaGetSymbolAddress((void**)&mih,    g_Mih);
    cudaGetSymbolAddress((void**)&mil,    g_Mil);
    cudaGetSymbolAddress((void**)&moh,    g_Moh);
    cudaGetSymbolAddress((void**)&mol,    g_Mol);
    cudaGetSymbolAddress((void**)&xh,     g_Xhi);
    cudaGetSymbolAddress((void**)&xl,     g_Xlo);
    cudaGetSymbolAddress((void**)&bch,    g_BChi);
    cudaGetSymbolAddress((void**)&bcl,    g_BClo);
    cudaGetSymbolAddress((void**)&P,      g_P);
    cudaGetSymbolAddress((void**)&agg,    g_agg);
    cudaGetSymbolAddress((void**)&x1,     g_x1);
    cudaGetSymbolAddress((void**)&sum,    g_sum);
    cudaGetSymbolAddress((void**)&sumsq,  g_sumsq);
    cudaGetSymbolAddress((void**)&cA,     g_cA);
    cudaGetSymbolAddress((void**)&cB,     g_cB);

    static int smem_set = 0;
    if (!smem_set) {
        cudaFuncSetAttribute(pwmma_k<0>, cudaFuncAttributeMaxDynamicSharedMemorySize, PW_SMEM);
        cudaFuncSetAttribute(pwmma_k<1>, cudaFuncAttributeMaxDynamicSharedMemorySize, PW_SMEM);
        cudaFuncSetAttribute(pwmma_k<2>, cudaFuncAttributeMaxDynamicSharedMemorySize, PW_SMEM);
        smem_set = 1;
    }
    int nsm = 148;
    cudaDeviceGetAttribute(&nsm, cudaDevAttrMultiProcessorCount, 0);

    float* out     = (float*)d_out;
    float* out_sub = out;
    float* out_rel = out + NB * D;
    float* out_x   = out + 2 * NB * D;

    // graph structure (layer-invariant)
    cudaMemsetAsync(deg, 0, 2 * NE * sizeof(float));
    cudaMemsetAsync(cin, 0, NE * sizeof(int));
    cudaMemsetAsync(cout, 0, NE * sizeof(int));
    degcnt_k<<<(TOT + 255) / 256, 256>>>(ei, deg, cin, cout);
    norm_k<<<(TOT + 255) / 256, 256>>>(ei, deg, nrm);
    scan2_k<<<2, SCAN_T>>>(cin, oin, curin, cout, oout, curout);
    fill_k<<<(TOT + 255) / 256, 256>>>(ei, curin, curout, cein, ceout);
    conv_x_k<<<NE, 128>>>(init_embed, xh, xl);

    for (int l = 0; l < 2; l++) {
        const float* x_in = l ? x1 : init_embed;
        const float* r_in = l ? r1 : init_rel;
        float* x_out = l ? out_x : x1;
        float* r_out = l ? r2 : r1;

        cudaMemcpyAsync(relbuf, r_in, R2 * D * sizeof(float), cudaMemcpyDeviceToDevice);
        cudaMemcpyAsync(relbuf + R2 * D, L[l][5], D * sizeof(float), cudaMemcpyDeviceToDevice);
        cudaMemsetAsync(sum, 0, D * sizeof(float));
        cudaMemsetAsync(sumsq, 0, D * sizeof(float));

        prep_bcat_split_k<<<(3 * KP * KP + 255) / 256, 256>>>(L[l][1], L[l][2], L[l][0],
                                                              L[l][5], bch, bcl);
        prep_wimg_k<<<(KP * KP + 255) / 256, 256>>>(L[l][4], whi, wlo);
        build_q_k<<<TOT, 128>>>(x_in, relbuf, qe, qr, qhi, qlo);
        // persistent wmma qual GEMM + fused P epilogue
        pwmma_k<2><<<nsm, 256, PW_SMEM>>>(qhi, qlo, whi, wlo, P, TOT,
                                          ei, et, x_in, relbuf, nrm);
        // per-dst segment sums of P -> bf16 split Min/Mout
        aggregate_k<<<AGG_BLOCKS, 256>>>(P, oin, cein, oout, ceout, mih, mil, moh, mol);
        // K600 as 3 persistent wmma passes: agg = Min@w_in + Mout@w_out + x@W2
        pwmma_k<0><<<nsm, 256, PW_SMEM>>>(mih, mil, bch, bcl, agg, NE,
                                          nullptr, nullptr, nullptr, nullptr, nullptr);
        pwmma_k<1><<<nsm, 256, PW_SMEM>>>(moh, mol, bch + KP * KP, bcl + KP * KP, agg, NE,
                                          nullptr, nullptr, nullptr, nullptr, nullptr);
        pwmma_k<1><<<nsm, 256, PW_SMEM>>>(xh, xl, bch + 2 * KP * KP, bcl + 2 * KP * KP,
                                          agg, NE,
                                          nullptr, nullptr, nullptr, nullptr, nullptr);
        // BN + tanh (layer 1 also emits x1 bf16 split for next layer)
        bn_stats_k<<<BN_BLOCKS, 128>>>(agg, sum, sumsq);
        bn_final_k<<<1, 224>>>(sum, sumsq, L[l][7], L[l][8], cA, cB);
        if (l == 0)
            bn_apply_k<true><<<(NE * D / 2 + 255) / 256, 256>>>(agg, cA, cB, x_out, xh, xl);
        else
            bn_apply_k<false><<<(NE * D / 2 + 255) / 256, 256>>>(agg, cA, cB, x_out,
                                                                 nullptr, nullptr);
        // rel update (tiny, FFMA2 path)
        gemm_k<1, 128, 256, 2><<<(R2 + 127) / 128, 256>>>(r_in, nullptr, nullptr,
                                                          L[l][3], r_out, R2);
    }

    gather_k<<<NB, 128>>>(out_x, sub, out_sub);
    gather_k<<<NB, 128>>>(r2, rel, out_rel);
}